// round 12
// baseline (speedup 1.0000x reference)
#include <cuda_runtime.h>
#include <math.h>

#define BB   256
#define HH   512
#define DD   512
#define NS   64
#define G5   2560
#define GRID 148
#define TPB  512

// dynamic smem:
//  big phase: A float [2][16][132] at 0 (16896 B), B float [2][16][132] at 16896
//  step phase: per half h at h*17408: A [2][16][68] (8704 B), B [2][16][68]
#define DYN_BYTES 36864
#define BIGB_OFF  16896
#define STB_OFF   8704
#define HALF_OFF  17408

typedef unsigned long long ull;

// ---------------- packed fp32 helpers ----------------
__device__ __forceinline__ ull dup2(float a) {
    ull d;
    asm("mov.b64 %0, {%1, %1};" : "=l"(d) : "f"(a));
    return d;
}
__device__ __forceinline__ void ffma2(ull& acc, ull a, ull b) {
    asm("fma.rn.f32x2 %0, %1, %2, %0;" : "+l"(acc) : "l"(a), "l"(b));
}
__device__ __forceinline__ float2 unpk(ull v) {
    float2 r;
    asm("mov.b64 {%0, %1}, %2;" : "=f"(r.x), "=f"(r.y) : "l"(v));
    return r;
}
#define HBAR(h) asm volatile("bar.sync %0, 256;" :: "r"((h) + 1) : "memory")

// ---------------- static device scratch ----------------
__device__ float g_h [BB * NS * HH];
__device__ float g_c [BB * NS * HH];
__device__ float g_ch[BB * NS * HH];
__device__ float g_cc[BB * NS * HH];
__device__ float g_vl[(size_t)BB * NS * G5];
__device__ float g_vr[(size_t)BB * NS * G5];
__device__ float g_pv[BB * 5120];               // split-K partial (ks=1)
__device__ float g_clog[BB * NS];
__device__ int   g_seq [BB * 32];
__device__ int4  g_jobs[BB * 2];
__device__ int   g_active[BB];
__device__ int   g_nact[32];
__device__ int   g_rowmap[BB * 32];
__device__ int   g_nrow;
// two-level barrier state: per-group counters on distinct 128B lines + root
__device__ int   g_bar_grp[8 * 32];             // use index g*32
__device__ int   g_bar_root = 0;
__device__ volatile int g_bar_gen = 0;

__device__ __forceinline__ float sigf(float x) { return 1.f / (1.f + expf(-x)); }

// ---------------- two-level software grid barrier ----------------
// 8 groups of contiguous bids (7x19 + 1x15). Arrival: <=19 serialized atomics
// per distinct line + 8 on root (~730 cyc) instead of 148 on one address (~4000).
__device__ __forceinline__ void gbar(int tid, int bid, int* gen)
{
    __syncthreads();
    if (tid == 0) {
        int target = *gen + 1;
        __threadfence();
        int g  = bid / 19;                  // 0..7 (g==7 has 15 members)
        int sz = (g < 7) ? 19 : 15;
        if (atomicAdd(&g_bar_grp[g * 32], 1) == sz - 1) {
            g_bar_grp[g * 32] = 0;          // members already spinning on gen
            if (atomicAdd(&g_bar_root, 1) == 7) {
                g_bar_root = 0;
                __threadfence();
                g_bar_gen = target;
            }
        }
        if (g_bar_gen - target < 0) {
            while (g_bar_gen - target < 0) __nanosleep(32);
        }
        __threadfence();                    // gpu-scope: drop stale L1 lines
        *gen = target;
    }
    __syncthreads();
}

// ---------------- big GEMM tile: 128x128, BK=16, 512 threads, M-packed f32x2 ----
#define BIGA(buf,k,r) Af[((buf)*16 + (k))*132 + (r)]
#define BIGB(buf,k,r) Bf[((buf)*16 + (k))*132 + (r)]
__device__ void gemm_big(int mode, int m0, int n0, int NROW, int tid,
    char* dynp, int* __restrict__ srow,
    const float* __restrict__ x, const float* __restrict__ Ww,
    const float* __restrict__ bw, const float* __restrict__ Wc)
{
    float* Af = (float*)dynp;
    float* Bf = (float*)(dynp + BIGB_OFF);

    __syncthreads();
    if (tid < 128) {
        int r = m0 + tid;
        srow[tid] = (r < NROW) ? g_rowmap[r] : g_rowmap[0];
    }
    __syncthreads();

    const int lrow = tid >> 2;        // 0..127
    const int kq   = (tid & 3) * 4;   // 0,4,8,12

    const float* aptr;
    {
        int m = srow[lrow];
        aptr = (mode == 0) ? x + (size_t)m * DD + kq
                           : g_h + (size_t)(((m >> 5) << 6) + (m & 31)) * HH + kq;
    }
    const float* bptr;
    {
        int n = n0 + lrow;
        if (mode == 0) bptr = Ww + (size_t)n * DD + kq;
        else bptr = (n < G5) ? Wc + (size_t)n * 1024 + kq
                             : Wc + (size_t)(n - G5) * 1024 + 512 + kq;
    }

    const int ty = tid >> 5;   // warp id -> rows ty*8 (broadcast)
    const int tx = tid & 31;   // lane -> cols tx*4

    ull acc[4][4];
#pragma unroll
    for (int i = 0; i < 4; i++)
#pragma unroll
        for (int j = 0; j < 4; j++) acc[i][j] = 0ull;

    float4 ra = *reinterpret_cast<const float4*>(aptr);
    float4 rb = *reinterpret_cast<const float4*>(bptr);
    BIGA(0, kq + 0, lrow) = ra.x; BIGA(0, kq + 1, lrow) = ra.y;
    BIGA(0, kq + 2, lrow) = ra.z; BIGA(0, kq + 3, lrow) = ra.w;
    BIGB(0, kq + 0, lrow) = rb.x; BIGB(0, kq + 1, lrow) = rb.y;
    BIGB(0, kq + 2, lrow) = rb.z; BIGB(0, kq + 3, lrow) = rb.w;
    __syncthreads();

    int buf = 0;
    for (int k0 = 16; k0 <= 512; k0 += 16) {
        const bool more = (k0 < 512);
        if (more) {
            ra = *reinterpret_cast<const float4*>(aptr + k0);
            rb = *reinterpret_cast<const float4*>(bptr + k0);
        }
#pragma unroll
        for (int kk = 0; kk < 16; kk++) {
            ull a[4];
            ulonglong2 t0 = *reinterpret_cast<const ulonglong2*>(&BIGA(buf, kk, ty * 8));
            ulonglong2 t1 = *reinterpret_cast<const ulonglong2*>(&BIGA(buf, kk, ty * 8 + 4));
            a[0] = t0.x; a[1] = t0.y; a[2] = t1.x; a[3] = t1.y;
            float4 b4 = *reinterpret_cast<const float4*>(&BIGB(buf, kk, tx * 4));
            ull bd[4];
            bd[0] = dup2(b4.x); bd[1] = dup2(b4.y); bd[2] = dup2(b4.z); bd[3] = dup2(b4.w);
#pragma unroll
            for (int i = 0; i < 4; i++)
#pragma unroll
                for (int j = 0; j < 4; j++)
                    ffma2(acc[i][j], a[i], bd[j]);
        }
        if (more) {
            BIGA(buf ^ 1, kq + 0, lrow) = ra.x; BIGA(buf ^ 1, kq + 1, lrow) = ra.y;
            BIGA(buf ^ 1, kq + 2, lrow) = ra.z; BIGA(buf ^ 1, kq + 3, lrow) = ra.w;
            BIGB(buf ^ 1, kq + 0, lrow) = rb.x; BIGB(buf ^ 1, kq + 1, lrow) = rb.y;
            BIGB(buf ^ 1, kq + 2, lrow) = rb.z; BIGB(buf ^ 1, kq + 3, lrow) = rb.w;
        }
        __syncthreads();
        buf ^= 1;
    }

    const int nb = n0 + tx * 4;
    float4 bi = make_float4(0.f, 0.f, 0.f, 0.f);
    if (mode == 0) bi = *reinterpret_cast<const float4*>(&bw[nb]);
#pragma unroll
    for (int p = 0; p < 4; p++) {
        float2 c0 = unpk(acc[p][0]), c1 = unpk(acc[p][1]);
        float2 c2 = unpk(acc[p][2]), c3 = unpk(acc[p][3]);
        float4 row0 = make_float4(c0.x + bi.x, c1.x + bi.y, c2.x + bi.z, c3.x + bi.w);
        float4 row1 = make_float4(c0.y + bi.x, c1.y + bi.y, c2.y + bi.z, c3.y + bi.w);
#pragma unroll
        for (int h2 = 0; h2 < 2; h2++) {
            int r = ty * 8 + 2 * p + h2;
            if (m0 + r < NROW) {
                int m = srow[r];
                int slot = ((m >> 5) << 6) + (m & 31);
                float4 v = h2 ? row1 : row0;
                if (mode == 0) {
                    float* dst = (nb < HH) ? (g_h + (size_t)slot * HH + nb)
                                           : (g_c + (size_t)slot * HH + (nb - HH));
                    *reinterpret_cast<float4*>(dst) = v;
                } else {
                    size_t base = (size_t)slot * G5;
                    float* dst = (nb < G5) ? (g_vl + base + nb) : (g_vr + base + (nb - G5));
                    *reinterpret_cast<float4*>(dst) = v;
                }
            }
        }
    }
}

// ---------------- step GEMM half-tile: 64x64xK256 (split-K), 256 threads ----
#define STA(buf,k,r) Af[((buf)*16 + (k))*68 + (r)]
#define STB(buf,k,r) Bf[((buf)*16 + (k))*68 + (r)]
__device__ void gemm_step(int step, int nact, int m0, int n0, int ks, int t, int half,
    char* hs, const float* __restrict__ Wc)
{
    float* Af = (float*)hs;
    float* Bf = (float*)(hs + STB_OFF);

    const int lrow = t >> 2;        // 0..63
    const int kq   = (t & 3) * 4;
    const int kofs = ks * 256;

    const float* aptr;
    {
        int m = m0 + lrow;
        int b = (m < nact) ? g_active[m] : g_active[0];
        aptr = g_h + (size_t)(b * NS + 32 + step) * HH + kofs + kq;
    }
    const float* bptr;
    {
        int n = n0 + lrow;
        bptr = (n < G5) ? Wc + (size_t)n * 1024 + kofs + kq
                        : Wc + (size_t)(n - G5) * 1024 + 512 + kofs + kq;
    }

    const int ty = t >> 4;   // rows ty*4
    const int tx = t & 15;   // cols tx*4

    ull acc[2][4];
#pragma unroll
    for (int i = 0; i < 2; i++)
#pragma unroll
        for (int j = 0; j < 4; j++) acc[i][j] = 0ull;

    float4 ra = *reinterpret_cast<const float4*>(aptr);
    float4 rb = *reinterpret_cast<const float4*>(bptr);
    STA(0, kq + 0, lrow) = ra.x; STA(0, kq + 1, lrow) = ra.y;
    STA(0, kq + 2, lrow) = ra.z; STA(0, kq + 3, lrow) = ra.w;
    STB(0, kq + 0, lrow) = rb.x; STB(0, kq + 1, lrow) = rb.y;
    STB(0, kq + 2, lrow) = rb.z; STB(0, kq + 3, lrow) = rb.w;
    HBAR(half);

    int buf = 0;
    for (int k0 = 16; k0 <= 256; k0 += 16) {
        const bool more = (k0 < 256);
        if (more) {
            ra = *reinterpret_cast<const float4*>(aptr + k0);
            rb = *reinterpret_cast<const float4*>(bptr + k0);
        }
#pragma unroll
        for (int kk = 0; kk < 16; kk++) {
            ull a[2];
            ulonglong2 t0 = *reinterpret_cast<const ulonglong2*>(&STA(buf, kk, ty * 4));
            a[0] = t0.x; a[1] = t0.y;
            float4 b4 = *reinterpret_cast<const float4*>(&STB(buf, kk, tx * 4));
            ull bd[4];
            bd[0] = dup2(b4.x); bd[1] = dup2(b4.y); bd[2] = dup2(b4.z); bd[3] = dup2(b4.w);
#pragma unroll
            for (int i = 0; i < 2; i++)
#pragma unroll
                for (int j = 0; j < 4; j++)
                    ffma2(acc[i][j], a[i], bd[j]);
        }
        if (more) {
            STA(buf ^ 1, kq + 0, lrow) = ra.x; STA(buf ^ 1, kq + 1, lrow) = ra.y;
            STA(buf ^ 1, kq + 2, lrow) = ra.z; STA(buf ^ 1, kq + 3, lrow) = ra.w;
            STB(buf ^ 1, kq + 0, lrow) = rb.x; STB(buf ^ 1, kq + 1, lrow) = rb.y;
            STB(buf ^ 1, kq + 2, lrow) = rb.z; STB(buf ^ 1, kq + 3, lrow) = rb.w;
        }
        HBAR(half);
        buf ^= 1;
    }

    const int nb = n0 + tx * 4;
#pragma unroll
    for (int p = 0; p < 2; p++) {
        float2 c0 = unpk(acc[p][0]), c1 = unpk(acc[p][1]);
        float2 c2 = unpk(acc[p][2]), c3 = unpk(acc[p][3]);
        float4 row0 = make_float4(c0.x, c1.x, c2.x, c3.x);
        float4 row1 = make_float4(c0.y, c1.y, c2.y, c3.y);
#pragma unroll
        for (int h2 = 0; h2 < 2; h2++) {
            int m = m0 + ty * 4 + 2 * p + h2;
            if (m < nact) {
                int b = g_active[m];
                float4 v = h2 ? row1 : row0;
                if (ks == 0) {
                    size_t base = (size_t)(b * NS + 32 + step) * G5;
                    float* dst = (nb < G5) ? (g_vl + base + nb) : (g_vr + base + (nb - G5));
                    *reinterpret_cast<float4*>(dst) = v;
                } else {
                    *reinterpret_cast<float4*>(g_pv + b * 5120 + nb) = v;
                }
            }
        }
    }
    HBAR(half);
}

// ---------------- pair gates + partial logit (t in 0..127) ----------------
__device__ __forceinline__ float pair_body(int b, int key, int Ls, int Rs, int t,
    const float* __restrict__ b_comp, const float* __restrict__ cq)
{
    const float4* vl  = reinterpret_cast<const float4*>(g_vl + (size_t)(b * NS + Ls) * G5);
    const float4* vr  = reinterpret_cast<const float4*>(g_vr + (size_t)(b * NS + Rs) * G5);
    const float4* bc  = reinterpret_cast<const float4*>(b_comp);
    const float4* cl4 = reinterpret_cast<const float4*>(g_c + (size_t)(b * NS + Ls) * HH);
    const float4* cr4 = reinterpret_cast<const float4*>(g_c + (size_t)(b * NS + Rs) * HH);
    const float4* q4  = reinterpret_cast<const float4*>(cq);

    float vi[4], vfl[4], vfr[4], vu[4], vo[4];
    {
        float* dsts[5] = {vi, vfl, vfr, vu, vo};
#pragma unroll
        for (int g = 0; g < 5; g++) {
            float4 a = vl[g * 128 + t], bb = vr[g * 128 + t], c = bc[g * 128 + t];
            dsts[g][0] = a.x + bb.x + c.x; dsts[g][1] = a.y + bb.y + c.y;
            dsts[g][2] = a.z + bb.z + c.z; dsts[g][3] = a.w + bb.w + c.w;
        }
    }
    float4 cl = cl4[t], cr = cr4[t], qv = q4[t];
    float clv[4] = {cl.x, cl.y, cl.z, cl.w};
    float crv[4] = {cr.x, cr.y, cr.z, cr.w};
    float qa[4]  = {qv.x, qv.y, qv.z, qv.w};
    float hh[4], cc[4], part = 0.f;
#pragma unroll
    for (int e = 0; e < 4; e++) {
        float c = clv[e] * sigf(vfl[e] + 1.f) + crv[e] * sigf(vfr[e] + 1.f)
                + tanhf(vu[e]) * sigf(vi[e]);
        float h = sigf(vo[e]) * tanhf(c);
        cc[e] = c; hh[e] = h;
        part = fmaf(qa[e], h, part);
    }
    reinterpret_cast<float4*>(g_ch + (size_t)(b * NS + key) * HH)[t] = make_float4(hh[0], hh[1], hh[2], hh[3]);
    reinterpret_cast<float4*>(g_cc + (size_t)(b * NS + key) * HH)[t] = make_float4(cc[0], cc[1], cc[2], cc[3]);
    return part;
}

// ---------------- plan for batch b at step i (one warp) ----------------
__device__ __forceinline__ void plan_do(int b, int i, int lane, const int* __restrict__ length)
{
    int ell = length[b];
    if (i + 1 < ell) {
        int npairs = 31 - i;
        int seqv = g_seq[b * 32 + lane];
        bool valid = (lane < ell - i - 1);
        float lg = valid ? g_clog[b * NS + seqv] : -1e9f;
        float mx = lg;
#pragma unroll
        for (int o = 16; o; o >>= 1) mx = fmaxf(mx, __shfl_xor_sync(0xffffffffu, mx, o));
        unsigned bal = __ballot_sync(0xffffffffu, lg == mx);
        int k = __ffs(bal) - 1;   // first-max = jnp.argmax

        int s    = 32 + i;
        int sk   = __shfl_sync(0xffffffffu, seqv, k);
        int skm1 = __shfl_sync(0xffffffffu, seqv, (k > 0) ? (k - 1) : 0);
        int skp2 = __shfl_sync(0xffffffffu, seqv, (k + 2 < 32) ? (k + 2) : 31);

        const float4* sh = reinterpret_cast<const float4*>(g_ch + (size_t)(b * NS + sk) * HH);
        const float4* sc = reinterpret_cast<const float4*>(g_cc + (size_t)(b * NS + sk) * HH);
        float4* dh = reinterpret_cast<float4*>(g_h + (size_t)(b * NS + s) * HH);
        float4* dc = reinterpret_cast<float4*>(g_c + (size_t)(b * NS + s) * HH);
#pragma unroll
        for (int r = 0; r < 4; r++) {
            dh[lane + 32 * r] = sh[lane + 32 * r];
            dc[lane + 32 * r] = sc[lane + 32 * r];
        }
        if (lane == 0) {
            int idx = atomicAdd(&g_nact[i], 1);
            g_active[idx] = b;
            g_jobs[b * 2]     = make_int4(skm1, skm1, s, (k >= 1) ? 1 : 0);
            g_jobs[b * 2 + 1] = make_int4(s, s, skp2, (k <= npairs - 2) ? 1 : 0);
        }
        int nxt = __shfl_down_sync(0xffffffffu, seqv, 1);
        g_seq[b * 32 + lane] = (lane < k) ? seqv : ((lane == k) ? s : nxt);
    } else if (lane == 0) {
        g_jobs[b * 2]     = make_int4(0, 0, 0, 0);
        g_jobs[b * 2 + 1] = make_int4(0, 0, 0, 0);
    }
}

// ---------------- the persistent kernel ----------------
__global__ __launch_bounds__(TPB, 1) void persist_k(
    const float* __restrict__ x, const int* __restrict__ length,
    const float* __restrict__ W_word, const float* __restrict__ b_word,
    const float* __restrict__ W_comp, const float* __restrict__ b_comp,
    const float* __restrict__ cq, float* __restrict__ out)
{
    extern __shared__ __align__(16) char dynp[];
    __shared__ int   srow[128];
    __shared__ float sws[16];

    const int tid  = threadIdx.x;
    const int bid  = blockIdx.x;
    const int half = tid >> 8;     // 0/1
    const int t256 = tid & 255;
    int gen = 0;
    if (tid == 0) gen = g_bar_gen;

    // ---- init: rowmap (block 0), seq (block 1), nact (block 2) ----
    if (bid == 0) {
        int* slen = (int*)dynp;
        if (tid < BB) slen[tid] = length[tid];
        __syncthreads();
        if (tid < BB) {
            int s = 0;
            for (int q = 0; q < tid; q++) s += slen[q];
            int l = slen[tid];
            for (int k = 0; k < l; k++) g_rowmap[s + k] = tid * 32 + k;
            if (tid == BB - 1) g_nrow = s + l;
        }
    }
    if (bid == 1) {
        for (int idx = tid; idx < BB * 32; idx += TPB) g_seq[idx] = idx & 31;
    }
    if (bid == 2 && tid < 32) g_nact[tid] = 0;
    gbar(tid, bid, &gen);

    const int NROW = g_nrow;
    const int MG   = (NROW + 127) >> 7;

    // ---- phase A: word projection over live rows ----
    for (int tt = bid; tt < MG * 8; tt += GRID)
        gemm_big(0, (tt >> 3) * 128, (tt & 7) * 128, NROW, tid, dynp, srow, x, W_word, b_word, W_comp);
    gbar(tid, bid, &gen);

    // ---- phase B: leaf transforms over live rows ----
    for (int tt = bid; tt < MG * 40; tt += GRID)
        gemm_big(1, (tt / 40) * 128, (tt % 40) * 128, NROW, tid, dynp, srow, x, W_word, b_word, W_comp);
    gbar(tid, bid, &gen);

    // ---- phase C: initial candidates (only pairs inside valid prefix) ----
    {
        const int grp = tid >> 7, t2 = tid & 127, w4 = (tid >> 5) & 3;
        for (int p = bid; p < 1984; p += GRID) {
            int j  = p * 4 + grp;
            int b  = j / 31;
            int jj = j - b * 31;
            bool valid = (jj + 1 < length[b]);
            float part = valid ? pair_body(b, jj, jj, jj + 1, t2, b_comp, cq) : 0.f;
#pragma unroll
            for (int o = 16; o; o >>= 1) part += __shfl_xor_sync(0xffffffffu, part, o);
            if ((t2 & 31) == 0) sws[grp * 4 + w4] = part;
            __syncthreads();
            if (t2 == 0 && valid)
                g_clog[b * NS + jj] = (sws[grp*4] + sws[grp*4+1] + sws[grp*4+2] + sws[grp*4+3])
                                      * 0.044194173824159216f;
            __syncthreads();
        }
    }
    gbar(tid, bid, &gen);

    // ---- plan(0): batch b on block b/2 (warp 0 of each half) ----
    {
        int b = bid * 2 + half;
        if (b < BB && t256 < 32) plan_do(b, 0, tid & 31, length);
    }
    gbar(tid, bid, &gen);

    // ---- main loop ----
    for (int i = 0; i < 30; i++) {
        // step GEMM: split-K=2, independent 64x64xK256 half-tiles
        {
            int nact   = g_nact[i];
            int ntile2 = (((nact + 63) >> 6) * 80) * 2;
            char* hs = dynp + half * HALF_OFF;
            for (int w = half * GRID + bid; w < ntile2; w += 2 * GRID) {
                int tile = w >> 1, ks = w & 1;
                gemm_step(i, nact, (tile / 80) * 64, (tile % 80) * 64, ks, t256, half, hs, W_comp);
            }
        }
        gbar(tid, bid, &gen);

        // PP: finalize split-K partials, pair jobs of step i, plan(i+1)
        {
            int b = bid * 2 + half;
            bool bact = (b < BB);
            bool bmerged = bact && (i + 1 < length[b]);

            if (bmerged) {
                int s = 32 + i;
                const float4* pv = reinterpret_cast<const float4*>(g_pv + b * 5120);
                float4* vl = reinterpret_cast<float4*>(g_vl + (size_t)(b * NS + s) * G5);
                float4* vr = reinterpret_cast<float4*>(g_vr + (size_t)(b * NS + s) * G5);
#pragma unroll
                for (int q = 0; q < 5; q++) {
                    int idx = q * 256 + t256;
                    float4 p = pv[idx];
                    float4* dst = (idx < 640) ? (vl + idx) : (vr + idx - 640);
                    float4 v = *dst;
                    v.x += p.x; v.y += p.y; v.z += p.z; v.w += p.w;
                    *dst = v;
                }
            }
            __syncthreads();

            const int grp = tid >> 7, t2 = tid & 127, w4 = (tid >> 5) & 3;
            int4 job = make_int4(0, 0, 0, 0);
            if (bact) job = g_jobs[b * 2 + (t256 >> 7)];
            bool jact = bact && job.w;
            float part = jact ? pair_body(b, job.x, job.y, job.z, t2, b_comp, cq) : 0.f;
#pragma unroll
            for (int o = 16; o; o >>= 1) part += __shfl_xor_sync(0xffffffffu, part, o);
            if ((t2 & 31) == 0) sws[grp * 4 + w4] = part;
            __syncthreads();
            if (t2 == 0 && jact)
                g_clog[b * NS + job.x] = (sws[grp*4] + sws[grp*4+1] + sws[grp*4+2] + sws[grp*4+3])
                                         * 0.044194173824159216f;
            __syncthreads();
            if (bact && t256 < 32) plan_do(b, i + 1, tid & 31, length);
        }
        gbar(tid, bid, &gen);
    }

    // ---- output: h of root slot ----
    {
        int b = bid * 2 + half;
        if (b < BB && t256 < 128) {
            int s = g_seq[b * 32];
            const float4* src = reinterpret_cast<const float4*>(g_h + (size_t)(b * NS + s) * HH);
            reinterpret_cast<float4*>(out)[b * 128 + t256] = src[t256];
        }
    }
}

// ---------------- launch ----------------
extern "C" void kernel_launch(void* const* d_in, const int* in_sizes, int n_in,
                              void* d_out, int out_size)
{
    const float* x      = (const float*)d_in[0];
    const int*   length = (const int*)  d_in[1];
    const float* W_word = (const float*)d_in[2];
    const float* b_word = (const float*)d_in[3];
    const float* W_comp = (const float*)d_in[4];
    const float* b_comp = (const float*)d_in[5];
    const float* cq     = (const float*)d_in[6];
    float* out = (float*)d_out;

    cudaFuncSetAttribute(persist_k, cudaFuncAttributeMaxDynamicSharedMemorySize, DYN_BYTES);
    persist_k<<<GRID, TPB, DYN_BYTES>>>(x, length, W_word, b_word, W_comp, b_comp, cq, out);
}

// round 13
// speedup vs baseline: 1.0065x; 1.0065x over previous
#include <cuda_runtime.h>
#include <math.h>

#define BB   256
#define HH   512
#define DD   512
#define NS   64
#define G5   2560
#define GRID 148
#define TPB  512

#define DYN_BYTES 36864
#define BIGB_OFF  16896
#define STB_OFF   8704
#define HALF_OFF  17408

typedef unsigned long long ull;

// ---------------- packed fp32 helpers ----------------
__device__ __forceinline__ ull dup2(float a) {
    ull d;
    asm("mov.b64 %0, {%1, %1};" : "=l"(d) : "f"(a));
    return d;
}
__device__ __forceinline__ void ffma2(ull& acc, ull a, ull b) {
    asm("fma.rn.f32x2 %0, %1, %2, %0;" : "+l"(acc) : "l"(a), "l"(b));
}
__device__ __forceinline__ float2 unpk(ull v) {
    float2 r;
    asm("mov.b64 {%0, %1}, %2;" : "=f"(r.x), "=f"(r.y) : "l"(v));
    return r;
}
#define HBAR(h) asm volatile("bar.sync %0, 256;" :: "r"((h) + 1) : "memory")

// ---------------- static device scratch ----------------
__device__ float g_h [BB * NS * HH];
__device__ float g_c [BB * NS * HH];
__device__ float g_ch[BB * NS * HH];
__device__ float g_cc[BB * NS * HH];
__device__ float g_vl[(size_t)BB * NS * G5];
__device__ float g_vr[(size_t)BB * NS * G5];
__device__ float g_pv[BB * 5120];               // split-K partial (ks=1)
__device__ float g_clog[BB * NS];
__device__ int   g_seq [BB * 32];
__device__ int4  g_jobs[BB * 2];
__device__ int   g_active[32 * BB];             // per-step compacted batch lists
__device__ int   g_actpos[BB];                  // batch -> row in its step's list
__device__ int   g_nact[32];
__device__ int   g_done[32 * 4];                // per-step per-Mtile completion counters
__device__ int   g_rowmap[BB * 32];
__device__ int   g_nrow;
__device__ int   g_bar_cnt = 0;
__device__ volatile int g_bar_gen = 0;

__device__ __forceinline__ float sigf(float x) { return 1.f / (1.f + expf(-x)); }

// ---------------- software grid barrier (single counter — proven) ----------------
__device__ __forceinline__ void gbar(int tid, int* gen)
{
    __syncthreads();
    if (tid == 0) {
        int target = *gen + 1;
        __threadfence();
        if (atomicAdd(&g_bar_cnt, 1) == GRID - 1) {
            g_bar_cnt = 0;
            __threadfence();
            g_bar_gen = target;
        } else {
            while (g_bar_gen - target < 0) __nanosleep(32);
            __threadfence();   // gpu-scope fence: drop stale L1 lines
        }
        *gen = target;
    }
    __syncthreads();
}

// ---------------- big GEMM tile: 128x128, BK=16, 512 threads, M-packed f32x2 ----
#define BIGA(buf,k,r) Af[((buf)*16 + (k))*132 + (r)]
#define BIGB(buf,k,r) Bf[((buf)*16 + (k))*132 + (r)]
__device__ void gemm_big(int mode, int m0, int n0, int NROW, int tid,
    char* dynp, int* __restrict__ srow,
    const float* __restrict__ x, const float* __restrict__ Ww,
    const float* __restrict__ bw, const float* __restrict__ Wc)
{
    float* Af = (float*)dynp;
    float* Bf = (float*)(dynp + BIGB_OFF);

    __syncthreads();
    if (tid < 128) {
        int r = m0 + tid;
        srow[tid] = (r < NROW) ? g_rowmap[r] : g_rowmap[0];
    }
    __syncthreads();

    const int lrow = tid >> 2;
    const int kq   = (tid & 3) * 4;

    const float* aptr;
    {
        int m = srow[lrow];
        aptr = (mode == 0) ? x + (size_t)m * DD + kq
                           : g_h + (size_t)(((m >> 5) << 6) + (m & 31)) * HH + kq;
    }
    const float* bptr;
    {
        int n = n0 + lrow;
        if (mode == 0) bptr = Ww + (size_t)n * DD + kq;
        else bptr = (n < G5) ? Wc + (size_t)n * 1024 + kq
                             : Wc + (size_t)(n - G5) * 1024 + 512 + kq;
    }

    const int ty = tid >> 5;
    const int tx = tid & 31;

    ull acc[4][4];
#pragma unroll
    for (int i = 0; i < 4; i++)
#pragma unroll
        for (int j = 0; j < 4; j++) acc[i][j] = 0ull;

    float4 ra = *reinterpret_cast<const float4*>(aptr);
    float4 rb = *reinterpret_cast<const float4*>(bptr);
    BIGA(0, kq + 0, lrow) = ra.x; BIGA(0, kq + 1, lrow) = ra.y;
    BIGA(0, kq + 2, lrow) = ra.z; BIGA(0, kq + 3, lrow) = ra.w;
    BIGB(0, kq + 0, lrow) = rb.x; BIGB(0, kq + 1, lrow) = rb.y;
    BIGB(0, kq + 2, lrow) = rb.z; BIGB(0, kq + 3, lrow) = rb.w;
    __syncthreads();

    int buf = 0;
    for (int k0 = 16; k0 <= 512; k0 += 16) {
        const bool more = (k0 < 512);
        if (more) {
            ra = *reinterpret_cast<const float4*>(aptr + k0);
            rb = *reinterpret_cast<const float4*>(bptr + k0);
        }
#pragma unroll
        for (int kk = 0; kk < 16; kk++) {
            ull a[4];
            ulonglong2 t0 = *reinterpret_cast<const ulonglong2*>(&BIGA(buf, kk, ty * 8));
            ulonglong2 t1 = *reinterpret_cast<const ulonglong2*>(&BIGA(buf, kk, ty * 8 + 4));
            a[0] = t0.x; a[1] = t0.y; a[2] = t1.x; a[3] = t1.y;
            float4 b4 = *reinterpret_cast<const float4*>(&BIGB(buf, kk, tx * 4));
            ull bd[4];
            bd[0] = dup2(b4.x); bd[1] = dup2(b4.y); bd[2] = dup2(b4.z); bd[3] = dup2(b4.w);
#pragma unroll
            for (int i = 0; i < 4; i++)
#pragma unroll
                for (int j = 0; j < 4; j++)
                    ffma2(acc[i][j], a[i], bd[j]);
        }
        if (more) {
            BIGA(buf ^ 1, kq + 0, lrow) = ra.x; BIGA(buf ^ 1, kq + 1, lrow) = ra.y;
            BIGA(buf ^ 1, kq + 2, lrow) = ra.z; BIGA(buf ^ 1, kq + 3, lrow) = ra.w;
            BIGB(buf ^ 1, kq + 0, lrow) = rb.x; BIGB(buf ^ 1, kq + 1, lrow) = rb.y;
            BIGB(buf ^ 1, kq + 2, lrow) = rb.z; BIGB(buf ^ 1, kq + 3, lrow) = rb.w;
        }
        __syncthreads();
        buf ^= 1;
    }

    const int nb = n0 + tx * 4;
    float4 bi = make_float4(0.f, 0.f, 0.f, 0.f);
    if (mode == 0) bi = *reinterpret_cast<const float4*>(&bw[nb]);
#pragma unroll
    for (int p = 0; p < 4; p++) {
        float2 c0 = unpk(acc[p][0]), c1 = unpk(acc[p][1]);
        float2 c2 = unpk(acc[p][2]), c3 = unpk(acc[p][3]);
        float4 row0 = make_float4(c0.x + bi.x, c1.x + bi.y, c2.x + bi.z, c3.x + bi.w);
        float4 row1 = make_float4(c0.y + bi.x, c1.y + bi.y, c2.y + bi.z, c3.y + bi.w);
#pragma unroll
        for (int h2 = 0; h2 < 2; h2++) {
            int r = ty * 8 + 2 * p + h2;
            if (m0 + r < NROW) {
                int m = srow[r];
                int slot = ((m >> 5) << 6) + (m & 31);
                float4 v = h2 ? row1 : row0;
                if (mode == 0) {
                    float* dst = (nb < HH) ? (g_h + (size_t)slot * HH + nb)
                                           : (g_c + (size_t)slot * HH + (nb - HH));
                    *reinterpret_cast<float4*>(dst) = v;
                } else {
                    size_t base = (size_t)slot * G5;
                    float* dst = (nb < G5) ? (g_vl + base + nb) : (g_vr + base + (nb - G5));
                    *reinterpret_cast<float4*>(dst) = v;
                }
            }
        }
    }
}

// ---------------- step GEMM half-tile: 64x64xK256 (split-K) + done-counter ----
#define STA(buf,k,r) Af[((buf)*16 + (k))*68 + (r)]
#define STB(buf,k,r) Bf[((buf)*16 + (k))*68 + (r)]
__device__ void gemm_step(int step, int nact, int m0, int n0, int ks, int t, int half,
    char* hs, const float* __restrict__ Wc)
{
    float* Af = (float*)hs;
    float* Bf = (float*)(hs + STB_OFF);

    const int lrow = t >> 2;
    const int kq   = (t & 3) * 4;
    const int kofs = ks * 256;
    const int* act = g_active + step * BB;

    const float* aptr;
    {
        int m = m0 + lrow;
        int b = act[(m < nact) ? m : 0];
        aptr = g_h + (size_t)(b * NS + 32 + step) * HH + kofs + kq;
    }
    const float* bptr;
    {
        int n = n0 + lrow;
        bptr = (n < G5) ? Wc + (size_t)n * 1024 + kofs + kq
                        : Wc + (size_t)(n - G5) * 1024 + 512 + kofs + kq;
    }

    const int ty = t >> 4;
    const int tx = t & 15;

    ull acc[2][4];
#pragma unroll
    for (int i = 0; i < 2; i++)
#pragma unroll
        for (int j = 0; j < 4; j++) acc[i][j] = 0ull;

    float4 ra = *reinterpret_cast<const float4*>(aptr);
    float4 rb = *reinterpret_cast<const float4*>(bptr);
    STA(0, kq + 0, lrow) = ra.x; STA(0, kq + 1, lrow) = ra.y;
    STA(0, kq + 2, lrow) = ra.z; STA(0, kq + 3, lrow) = ra.w;
    STB(0, kq + 0, lrow) = rb.x; STB(0, kq + 1, lrow) = rb.y;
    STB(0, kq + 2, lrow) = rb.z; STB(0, kq + 3, lrow) = rb.w;
    HBAR(half);

    int buf = 0;
    for (int k0 = 16; k0 <= 256; k0 += 16) {
        const bool more = (k0 < 256);
        if (more) {
            ra = *reinterpret_cast<const float4*>(aptr + k0);
            rb = *reinterpret_cast<const float4*>(bptr + k0);
        }
#pragma unroll
        for (int kk = 0; kk < 16; kk++) {
            ull a[2];
            ulonglong2 t0 = *reinterpret_cast<const ulonglong2*>(&STA(buf, kk, ty * 4));
            a[0] = t0.x; a[1] = t0.y;
            float4 b4 = *reinterpret_cast<const float4*>(&STB(buf, kk, tx * 4));
            ull bd[4];
            bd[0] = dup2(b4.x); bd[1] = dup2(b4.y); bd[2] = dup2(b4.z); bd[3] = dup2(b4.w);
#pragma unroll
            for (int i = 0; i < 2; i++)
#pragma unroll
                for (int j = 0; j < 4; j++)
                    ffma2(acc[i][j], a[i], bd[j]);
        }
        if (more) {
            STA(buf ^ 1, kq + 0, lrow) = ra.x; STA(buf ^ 1, kq + 1, lrow) = ra.y;
            STA(buf ^ 1, kq + 2, lrow) = ra.z; STA(buf ^ 1, kq + 3, lrow) = ra.w;
            STB(buf ^ 1, kq + 0, lrow) = rb.x; STB(buf ^ 1, kq + 1, lrow) = rb.y;
            STB(buf ^ 1, kq + 2, lrow) = rb.z; STB(buf ^ 1, kq + 3, lrow) = rb.w;
        }
        HBAR(half);
        buf ^= 1;
    }

    const int nb = n0 + tx * 4;
#pragma unroll
    for (int p = 0; p < 2; p++) {
        float2 c0 = unpk(acc[p][0]), c1 = unpk(acc[p][1]);
        float2 c2 = unpk(acc[p][2]), c3 = unpk(acc[p][3]);
        float4 row0 = make_float4(c0.x, c1.x, c2.x, c3.x);
        float4 row1 = make_float4(c0.y, c1.y, c2.y, c3.y);
#pragma unroll
        for (int h2 = 0; h2 < 2; h2++) {
            int m = m0 + ty * 4 + 2 * p + h2;
            if (m < nact) {
                int b = act[m];
                float4 v = h2 ? row1 : row0;
                if (ks == 0) {
                    size_t base = (size_t)(b * NS + 32 + step) * G5;
                    float* dst = (nb < G5) ? (g_vl + base + nb) : (g_vr + base + (nb - G5));
                    *reinterpret_cast<float4*>(dst) = v;
                } else {
                    *reinterpret_cast<float4*>(g_pv + b * 5120 + nb) = v;
                }
            }
        }
    }
    __threadfence();             // publish stores before signaling
    HBAR(half);                  // all threads' stores+fences done; also smem reuse guard
    if (t == 0) atomicAdd(&g_done[step * 4 + (m0 >> 6)], 1);
}

// ---------------- pair gates + partial logit (t in 0..127) ----------------
__device__ __forceinline__ float pair_body(int b, int key, int Ls, int Rs, int t,
    const float* __restrict__ b_comp, const float* __restrict__ cq)
{
    const float4* vl  = reinterpret_cast<const float4*>(g_vl + (size_t)(b * NS + Ls) * G5);
    const float4* vr  = reinterpret_cast<const float4*>(g_vr + (size_t)(b * NS + Rs) * G5);
    const float4* bc  = reinterpret_cast<const float4*>(b_comp);
    const float4* cl4 = reinterpret_cast<const float4*>(g_c + (size_t)(b * NS + Ls) * HH);
    const float4* cr4 = reinterpret_cast<const float4*>(g_c + (size_t)(b * NS + Rs) * HH);
    const float4* q4  = reinterpret_cast<const float4*>(cq);

    float vi[4], vfl[4], vfr[4], vu[4], vo[4];
    {
        float* dsts[5] = {vi, vfl, vfr, vu, vo};
#pragma unroll
        for (int g = 0; g < 5; g++) {
            float4 a = vl[g * 128 + t], bb = vr[g * 128 + t], c = bc[g * 128 + t];
            dsts[g][0] = a.x + bb.x + c.x; dsts[g][1] = a.y + bb.y + c.y;
            dsts[g][2] = a.z + bb.z + c.z; dsts[g][3] = a.w + bb.w + c.w;
        }
    }
    float4 cl = cl4[t], cr = cr4[t], qv = q4[t];
    float clv[4] = {cl.x, cl.y, cl.z, cl.w};
    float crv[4] = {cr.x, cr.y, cr.z, cr.w};
    float qa[4]  = {qv.x, qv.y, qv.z, qv.w};
    float hh[4], cc[4], part = 0.f;
#pragma unroll
    for (int e = 0; e < 4; e++) {
        float c = clv[e] * sigf(vfl[e] + 1.f) + crv[e] * sigf(vfr[e] + 1.f)
                + tanhf(vu[e]) * sigf(vi[e]);
        float h = sigf(vo[e]) * tanhf(c);
        cc[e] = c; hh[e] = h;
        part = fmaf(qa[e], h, part);
    }
    reinterpret_cast<float4*>(g_ch + (size_t)(b * NS + key) * HH)[t] = make_float4(hh[0], hh[1], hh[2], hh[3]);
    reinterpret_cast<float4*>(g_cc + (size_t)(b * NS + key) * HH)[t] = make_float4(cc[0], cc[1], cc[2], cc[3]);
    return part;
}

// ---------------- plan for batch b at step i (one warp) ----------------
__device__ __forceinline__ void plan_do(int b, int i, int lane, const int* __restrict__ length)
{
    int ell = length[b];
    if (i + 1 < ell) {
        int npairs = 31 - i;
        int seqv = g_seq[b * 32 + lane];
        bool valid = (lane < ell - i - 1);
        float lg = valid ? g_clog[b * NS + seqv] : -1e9f;
        float mx = lg;
#pragma unroll
        for (int o = 16; o; o >>= 1) mx = fmaxf(mx, __shfl_xor_sync(0xffffffffu, mx, o));
        unsigned bal = __ballot_sync(0xffffffffu, lg == mx);
        int k = __ffs(bal) - 1;   // first-max = jnp.argmax

        int s    = 32 + i;
        int sk   = __shfl_sync(0xffffffffu, seqv, k);
        int skm1 = __shfl_sync(0xffffffffu, seqv, (k > 0) ? (k - 1) : 0);
        int skp2 = __shfl_sync(0xffffffffu, seqv, (k + 2 < 32) ? (k + 2) : 31);

        const float4* sh = reinterpret_cast<const float4*>(g_ch + (size_t)(b * NS + sk) * HH);
        const float4* sc = reinterpret_cast<const float4*>(g_cc + (size_t)(b * NS + sk) * HH);
        float4* dh = reinterpret_cast<float4*>(g_h + (size_t)(b * NS + s) * HH);
        float4* dc = reinterpret_cast<float4*>(g_c + (size_t)(b * NS + s) * HH);
#pragma unroll
        for (int r = 0; r < 4; r++) {
            dh[lane + 32 * r] = sh[lane + 32 * r];
            dc[lane + 32 * r] = sc[lane + 32 * r];
        }
        if (lane == 0) {
            int idx = atomicAdd(&g_nact[i], 1);
            g_active[i * BB + idx] = b;
            g_actpos[b] = idx;
            g_jobs[b * 2]     = make_int4(skm1, skm1, s, (k >= 1) ? 1 : 0);
            g_jobs[b * 2 + 1] = make_int4(s, s, skp2, (k <= npairs - 2) ? 1 : 0);
        }
        int nxt = __shfl_down_sync(0xffffffffu, seqv, 1);
        g_seq[b * 32 + lane] = (lane < k) ? seqv : ((lane == k) ? s : nxt);
    } else if (lane == 0) {
        g_jobs[b * 2]     = make_int4(0, 0, 0, 0);
        g_jobs[b * 2 + 1] = make_int4(0, 0, 0, 0);
    }
}

// ---------------- the persistent kernel ----------------
__global__ __launch_bounds__(TPB, 1) void persist_k(
    const float* __restrict__ x, const int* __restrict__ length,
    const float* __restrict__ W_word, const float* __restrict__ b_word,
    const float* __restrict__ W_comp, const float* __restrict__ b_comp,
    const float* __restrict__ cq, float* __restrict__ out)
{
    extern __shared__ __align__(16) char dynp[];
    __shared__ int   srow[128];
    __shared__ float sws[16];

    const int tid  = threadIdx.x;
    const int bid  = blockIdx.x;
    const int half = tid >> 8;
    const int t256 = tid & 255;
    int gen = 0;
    if (tid == 0) gen = g_bar_gen;

    // ---- init ----
    if (bid == 0) {
        int* slen = (int*)dynp;
        if (tid < BB) slen[tid] = length[tid];
        __syncthreads();
        if (tid < BB) {
            int s = 0;
            for (int q = 0; q < tid; q++) s += slen[q];
            int l = slen[tid];
            for (int k = 0; k < l; k++) g_rowmap[s + k] = tid * 32 + k;
            if (tid == BB - 1) g_nrow = s + l;
        }
    }
    if (bid == 1) {
        for (int idx = tid; idx < BB * 32; idx += TPB) g_seq[idx] = idx & 31;
    }
    if (bid == 2 && tid < 32) g_nact[tid] = 0;
    if (bid == 3 && tid < 128) g_done[tid] = 0;
    gbar(tid, &gen);

    const int NROW = g_nrow;
    const int MG   = (NROW + 127) >> 7;

    // ---- phase A: word projection over live rows ----
    for (int tt = bid; tt < MG * 8; tt += GRID)
        gemm_big(0, (tt >> 3) * 128, (tt & 7) * 128, NROW, tid, dynp, srow, x, W_word, b_word, W_comp);
    gbar(tid, &gen);

    // ---- phase B: leaf transforms over live rows ----
    for (int tt = bid; tt < MG * 40; tt += GRID)
        gemm_big(1, (tt / 40) * 128, (tt % 40) * 128, NROW, tid, dynp, srow, x, W_word, b_word, W_comp);
    gbar(tid, &gen);

    // ---- phase C: initial candidates ----
    {
        const int grp = tid >> 7, t2 = tid & 127, w4 = (tid >> 5) & 3;
        for (int p = bid; p < 1984; p += GRID) {
            int j  = p * 4 + grp;
            int b  = j / 31;
            int jj = j - b * 31;
            bool valid = (jj + 1 < length[b]);
            float part = valid ? pair_body(b, jj, jj, jj + 1, t2, b_comp, cq) : 0.f;
#pragma unroll
            for (int o = 16; o; o >>= 1) part += __shfl_xor_sync(0xffffffffu, part, o);
            if ((t2 & 31) == 0) sws[grp * 4 + w4] = part;
            __syncthreads();
            if (t2 == 0 && valid)
                g_clog[b * NS + jj] = (sws[grp*4] + sws[grp*4+1] + sws[grp*4+2] + sws[grp*4+3])
                                      * 0.044194173824159216f;
            __syncthreads();
        }
    }
    gbar(tid, &gen);

    // ---- plan(0) ----
    {
        int b = bid * 2 + half;
        if (b < BB && t256 < 32) plan_do(b, 0, tid & 31, length);
    }
    gbar(tid, &gen);

    // ---- main loop: ONE grid barrier per iteration ----
    for (int i = 0; i < 30; i++) {
        // step GEMM: split-K=2 half-tiles; each signals its Mtile counter
        {
            int nact   = g_nact[i];
            int ntile2 = (((nact + 63) >> 6) * 80) * 2;
            char* hs = dynp + half * HALF_OFF;
            for (int w = half * GRID + bid; w < ntile2; w += 2 * GRID) {
                int tile = w >> 1, ks = w & 1;
                gemm_step(i, nact, (tile / 80) * 64, (tile % 80) * 64, ks, t256, half, hs, W_comp);
            }
        }

        // PP: fine-grained wait on own Mtile, finalize, pair, plan(i+1)
        {
            int b = bid * 2 + half;
            bool bact = (b < BB);
            bool bmerged = bact && (i + 1 < length[b]);

            if (bmerged && t256 == 0) {
                int mt = g_actpos[b] >> 6;
                volatile int* dcnt = &g_done[i * 4 + mt];
                while (*dcnt < 160) __nanosleep(20);
            }
            HBAR(half);
            __threadfence();     // acquire: invalidate stale L1 (g_vl/g_vr/g_pv)

            if (bmerged) {
                int s = 32 + i;
                const float4* pv = reinterpret_cast<const float4*>(g_pv + b * 5120);
                float4* vl = reinterpret_cast<float4*>(g_vl + (size_t)(b * NS + s) * G5);
                float4* vr = reinterpret_cast<float4*>(g_vr + (size_t)(b * NS + s) * G5);
#pragma unroll
                for (int q = 0; q < 5; q++) {
                    int idx = q * 256 + t256;
                    float4 p = pv[idx];
                    float4* dst = (idx < 640) ? (vl + idx) : (vr + idx - 640);
                    float4 v = *dst;
                    v.x += p.x; v.y += p.y; v.z += p.z; v.w += p.w;
                    *dst = v;
                }
            }
            __syncthreads();

            const int grp = tid >> 7, t2 = tid & 127, w4 = (tid >> 5) & 3;
            int4 job = make_int4(0, 0, 0, 0);
            if (bact) job = g_jobs[b * 2 + (t256 >> 7)];
            bool jact = bact && job.w;
            float part = jact ? pair_body(b, job.x, job.y, job.z, t2, b_comp, cq) : 0.f;
#pragma unroll
            for (int o = 16; o; o >>= 1) part += __shfl_xor_sync(0xffffffffu, part, o);
            if ((t2 & 31) == 0) sws[grp * 4 + w4] = part;
            __syncthreads();
            if (t2 == 0 && jact)
                g_clog[b * NS + job.x] = (sws[grp*4] + sws[grp*4+1] + sws[grp*4+2] + sws[grp*4+3])
                                         * 0.044194173824159216f;
            __syncthreads();
            if (bact && t256 < 32) plan_do(b, i + 1, tid & 31, length);
        }
        gbar(tid, &gen);
    }

    // ---- output ----
    {
        int b = bid * 2 + half;
        if (b < BB && t256 < 128) {
            int s = g_seq[b * 32];
            const float4* src = reinterpret_cast<const float4*>(g_h + (size_t)(b * NS + s) * HH);
            reinterpret_cast<float4*>(out)[b * 128 + t256] = src[t256];
        }
    }
}

// ---------------- launch ----------------
extern "C" void kernel_launch(void* const* d_in, const int* in_sizes, int n_in,
                              void* d_out, int out_size)
{
    const float* x      = (const float*)d_in[0];
    const int*   length = (const int*)  d_in[1];
    const float* W_word = (const float*)d_in[2];
    const float* b_word = (const float*)d_in[3];
    const float* W_comp = (const float*)d_in[4];
    const float* b_comp = (const float*)d_in[5];
    const float* cq     = (const float*)d_in[6];
    float* out = (float*)d_out;

    cudaFuncSetAttribute(persist_k, cudaFuncAttributeMaxDynamicSharedMemorySize, DYN_BYTES);
    persist_k<<<GRID, TPB, DYN_BYTES>>>(x, length, W_word, b_word, W_comp, b_comp, cq, out);
}

// round 14
// speedup vs baseline: 1.0224x; 1.0159x over previous
#include <cuda_runtime.h>
#include <cuda_bf16.h>
#include <math.h>

#define BB   256
#define HH   512
#define DD   512
#define NS   64
#define G5   2560
#define GRID 148
#define TPB  512

// dyn smem: mma big tiles: A 2buf x 3split x 128row x 48B = 36864, B same at +36864
// step phase reuses [0, 34816)
#define DYN_BYTES 73728
#define MMA_B_OFF 36864
#define MMA_BUFS  18432
#define MMA_SPL   6144
#define STB_OFF   8704
#define HALF_OFF  17408

// split-array strides (elements)
#define XS (8192 * 512)
#define WW (1024 * 512)
#define WC (5120 * 512)
#define HS (8192 * 512)

typedef unsigned long long ull;

// ---------------- helpers ----------------
__device__ __forceinline__ ull dup2(float a) {
    ull d; asm("mov.b64 %0, {%1, %1};" : "=l"(d) : "f"(a)); return d;
}
__device__ __forceinline__ void ffma2(ull& acc, ull a, ull b) {
    asm("fma.rn.f32x2 %0, %1, %2, %0;" : "+l"(acc) : "l"(a), "l"(b));
}
__device__ __forceinline__ float2 unpk(ull v) {
    float2 r; asm("mov.b64 {%0, %1}, %2;" : "=f"(r.x), "=f"(r.y) : "l"(v)); return r;
}
__device__ __forceinline__ unsigned smem_u32(const void* p) {
    unsigned a;
    asm("{ .reg .u64 t; cvta.to.shared.u64 t, %1; cvt.u32.u64 %0, t; }" : "=r"(a) : "l"(p));
    return a;
}
#define HBAR(h) asm volatile("bar.sync %0, 256;" :: "r"((h) + 1) : "memory")

#define LDSM4(r, addr) asm volatile( \
    "ldmatrix.sync.aligned.m8n8.x4.shared.b16 {%0,%1,%2,%3}, [%4];" \
    : "=r"((r)[0]), "=r"((r)[1]), "=r"((r)[2]), "=r"((r)[3]) : "r"(addr))

#define MMA16816(d, a, b0, b1) asm volatile( \
    "mma.sync.aligned.m16n8k16.row.col.f32.bf16.bf16.f32 " \
    "{%0,%1,%2,%3}, {%4,%5,%6,%7}, {%8,%9}, {%0,%1,%2,%3};" \
    : "+f"((d)[0]), "+f"((d)[1]), "+f"((d)[2]), "+f"((d)[3]) \
    : "r"((a)[0]), "r"((a)[1]), "r"((a)[2]), "r"((a)[3]), "r"(b0), "r"(b1))

__device__ __forceinline__ ull pk2(__nv_bfloat162 a, __nv_bfloat162 b) {
    unsigned x = *reinterpret_cast<unsigned*>(&a);
    unsigned y = *reinterpret_cast<unsigned*>(&b);
    return (ull)x | ((ull)y << 32);
}
// fp32x4 -> 3-term bf16 split (4 elems per term, packed as ull)
__device__ __forceinline__ void split4(float4 f, ull& o0, ull& o1, ull& o2)
{
    __nv_bfloat162 p0 = __floats2bfloat162_rn(f.x, f.y);
    __nv_bfloat162 q0 = __floats2bfloat162_rn(f.z, f.w);
    float ax = f.x - __bfloat162float(p0.x), ay = f.y - __bfloat162float(p0.y);
    float az = f.z - __bfloat162float(q0.x), aw = f.w - __bfloat162float(q0.y);
    __nv_bfloat162 p1 = __floats2bfloat162_rn(ax, ay);
    __nv_bfloat162 q1 = __floats2bfloat162_rn(az, aw);
    float bx = ax - __bfloat162float(p1.x), by = ay - __bfloat162float(p1.y);
    float bz = az - __bfloat162float(q1.x), bw2 = aw - __bfloat162float(q1.y);
    __nv_bfloat162 p2 = __floats2bfloat162_rn(bx, by);
    __nv_bfloat162 q2 = __floats2bfloat162_rn(bz, bw2);
    o0 = pk2(p0, q0); o1 = pk2(p1, q1); o2 = pk2(p2, q2);
}

// ---------------- static device scratch ----------------
__device__ float g_h [BB * NS * HH];
__device__ float g_c [BB * NS * HH];
__device__ float g_ch[BB * NS * HH];
__device__ float g_cc[BB * NS * HH];
__device__ float g_vl[(size_t)BB * NS * G5];
__device__ float g_vr[(size_t)BB * NS * G5];
__device__ float g_pv[BB * 5120];
__device__ float g_clog[BB * NS];
__device__ int   g_seq [BB * 32];
__device__ int4  g_jobs[BB * 2];
__device__ int   g_active[BB];
__device__ int   g_nact[32];
__device__ int   g_rowmap[BB * 32];
__device__ int   g_nrow;
__device__ int   g_bar_cnt = 0;
__device__ volatile int g_bar_gen = 0;
// pre-split bf16 operands (3 terms each)
__device__ __nv_bfloat16 g_xs [3 * XS];
__device__ __nv_bfloat16 g_wws[3 * WW];
__device__ __nv_bfloat16 g_wcs[3 * WC];
__device__ __nv_bfloat16 g_hs [3 * HS];

__device__ __forceinline__ float sigf(float x) { return 1.f / (1.f + expf(-x)); }

// ---------------- software grid barrier (single counter — proven) ----------------
__device__ __forceinline__ void gbar(int tid, int* gen)
{
    __syncthreads();
    if (tid == 0) {
        int target = *gen + 1;
        __threadfence();
        if (atomicAdd(&g_bar_cnt, 1) == GRID - 1) {
            g_bar_cnt = 0;
            __threadfence();
            g_bar_gen = target;
        } else {
            while (g_bar_gen - target < 0) __nanosleep(32);
            __threadfence();
        }
        *gen = target;
    }
    __syncthreads();
}

// ---------------- big GEMM tile via mma.sync: 128x128xK512, bf16 x3 split ----
// mode 0: A = g_xs[rowmap], B = g_wws, +bias -> g_h/g_c
// mode 1: A = g_hs[rowmap], B = g_wcs           -> g_vl/g_vr
__device__ void gemm_big_mma(int mode, int m0, int n0, int NROW, int tid,
    char* dynp, unsigned dynu, int* __restrict__ srow, const float* __restrict__ bw)
{
    __syncthreads();
    if (tid < 128) {
        int r = m0 + tid;
        srow[tid] = (r < NROW) ? g_rowmap[r] : g_rowmap[0];
    }
    __syncthreads();

    const int arow = tid >> 2;        // 0..127
    const int kq   = (tid & 3) * 4;   // 0,4,8,12
    const __nv_bfloat16 *aS0, *bS0;
    {
        size_t aoff = (size_t)srow[arow] * 512 + kq;
        size_t boff = (size_t)(n0 + arow) * 512 + kq;
        aS0 = (mode == 0 ? g_xs : g_hs) + aoff;
        bS0 = (mode == 0 ? g_wws : g_wcs) + boff;
    }
    const size_t aStr = (mode == 0) ? XS : HS;
    const size_t bStr = (mode == 0) ? WW : WC;
    char* stsA = dynp + arow * 48 + kq * 2;
    char* stsB = dynp + MMA_B_OFF + arow * 48 + kq * 2;

    const int lane = tid & 31, wid = tid >> 5;
    const int wm = wid >> 2, wn = wid & 3;
    // ldmatrix lane base addresses (u32 shared)
    const unsigned ldA = dynu + (unsigned)((wm * 32 + (lane & 15)) * 48 + (lane >> 4) * 16);
    const int lrB = (lane & 7) + ((lane >> 4) << 3);
    const unsigned ldB = dynu + MMA_B_OFF + (unsigned)((wn * 32 + lrB) * 48 + ((lane >> 3) & 1) * 16);

    float acc[2][4][4];
#pragma unroll
    for (int i = 0; i < 2; i++)
#pragma unroll
        for (int j = 0; j < 4; j++)
#pragma unroll
            for (int q = 0; q < 4; q++) acc[i][j][q] = 0.f;

    // stage chunk 0 into buf 0
#pragma unroll
    for (int s = 0; s < 3; s++) {
        *reinterpret_cast<ull*>(stsA + s * MMA_SPL) = *reinterpret_cast<const ull*>(aS0 + s * aStr);
        *reinterpret_cast<ull*>(stsB + s * MMA_SPL) = *reinterpret_cast<const ull*>(bS0 + s * bStr);
    }
    __syncthreads();

    for (int kc = 0; kc < 32; kc++) {
        const int bo = (kc & 1) * MMA_BUFS;
        const bool more = (kc < 31);
        ull pa[3], pb[3];
        if (more) {
            int ko = (kc + 1) * 16;
#pragma unroll
            for (int s = 0; s < 3; s++) {
                pa[s] = *reinterpret_cast<const ull*>(aS0 + s * aStr + ko);
                pb[s] = *reinterpret_cast<const ull*>(bS0 + s * bStr + ko);
            }
        }
        unsigned a[3][2][4];
#pragma unroll
        for (int s = 0; s < 3; s++)
#pragma unroll
            for (int mt = 0; mt < 2; mt++)
                LDSM4(a[s][mt], ldA + bo + s * MMA_SPL + mt * 768);
#pragma unroll
        for (int sb = 0; sb < 3; sb++) {
            unsigned b[2][4];
#pragma unroll
            for (int np = 0; np < 2; np++)
                LDSM4(b[np], ldB + bo + sb * MMA_SPL + np * 768);
#pragma unroll
            for (int sa = 0; sa < 3; sa++) {
                if (sa + sb < 3) {
#pragma unroll
                    for (int mt = 0; mt < 2; mt++)
#pragma unroll
                        for (int np = 0; np < 2; np++) {
                            MMA16816(acc[mt][np * 2],     a[sa][mt], b[np][0], b[np][1]);
                            MMA16816(acc[mt][np * 2 + 1], a[sa][mt], b[np][2], b[np][3]);
                        }
                }
            }
        }
        if (more) {
            int bo2 = ((kc + 1) & 1) * MMA_BUFS;
#pragma unroll
            for (int s = 0; s < 3; s++) {
                *reinterpret_cast<ull*>(stsA + bo2 + s * MMA_SPL) = pa[s];
                *reinterpret_cast<ull*>(stsB + bo2 + s * MMA_SPL) = pb[s];
            }
        }
        __syncthreads();
    }

    // epilogue: thread holds D rows (wm*32+mt*16+lane/4, +8), cols (wn*32+nt8*8+2*(lane&3))
#pragma unroll
    for (int mt = 0; mt < 2; mt++)
#pragma unroll
        for (int nt8 = 0; nt8 < 4; nt8++) {
            int col = wn * 32 + nt8 * 8 + (lane & 3) * 2;
            int nc  = n0 + col;
#pragma unroll
            for (int hfl = 0; hfl < 2; hfl++) {
                int r = wm * 32 + mt * 16 + (lane >> 2) + hfl * 8;
                if (m0 + r < NROW) {
                    int m = srow[r];
                    int slot = ((m >> 5) << 6) + (m & 31);
                    float v0 = acc[mt][nt8][hfl * 2], v1 = acc[mt][nt8][hfl * 2 + 1];
                    if (mode == 0) {
                        v0 += bw[nc]; v1 += bw[nc + 1];
                        float* dst = (nc < HH) ? (g_h + (size_t)slot * HH + nc)
                                               : (g_c + (size_t)slot * HH + (nc - HH));
                        *reinterpret_cast<float2*>(dst) = make_float2(v0, v1);
                    } else {
                        size_t base = (size_t)slot * G5;
                        float* dst = (nc < G5) ? (g_vl + base + nc) : (g_vr + base + (nc - G5));
                        *reinterpret_cast<float2*>(dst) = make_float2(v0, v1);
                    }
                }
            }
        }
    __syncthreads();
}

// ---------------- step GEMM half-tile: 64x64xK256 (split-K), FFMA2, unchanged ----
#define STA(buf,k,r) Af[((buf)*16 + (k))*68 + (r)]
#define STB(buf,k,r) Bf[((buf)*16 + (k))*68 + (r)]
__device__ void gemm_step(int step, int nact, int m0, int n0, int ks, int t, int half,
    char* hs, const float* __restrict__ Wc)
{
    float* Af = (float*)hs;
    float* Bf = (float*)(hs + STB_OFF);

    const int lrow = t >> 2;
    const int kq   = (t & 3) * 4;
    const int kofs = ks * 256;

    const float* aptr;
    {
        int m = m0 + lrow;
        int b = (m < nact) ? g_active[m] : g_active[0];
        aptr = g_h + (size_t)(b * NS + 32 + step) * HH + kofs + kq;
    }
    const float* bptr;
    {
        int n = n0 + lrow;
        bptr = (n < G5) ? Wc + (size_t)n * 1024 + kofs + kq
                        : Wc + (size_t)(n - G5) * 1024 + 512 + kofs + kq;
    }

    const int ty = t >> 4;
    const int tx = t & 15;

    ull acc[2][4];
#pragma unroll
    for (int i = 0; i < 2; i++)
#pragma unroll
        for (int j = 0; j < 4; j++) acc[i][j] = 0ull;

    float4 ra = *reinterpret_cast<const float4*>(aptr);
    float4 rb = *reinterpret_cast<const float4*>(bptr);
    STA(0, kq + 0, lrow) = ra.x; STA(0, kq + 1, lrow) = ra.y;
    STA(0, kq + 2, lrow) = ra.z; STA(0, kq + 3, lrow) = ra.w;
    STB(0, kq + 0, lrow) = rb.x; STB(0, kq + 1, lrow) = rb.y;
    STB(0, kq + 2, lrow) = rb.z; STB(0, kq + 3, lrow) = rb.w;
    HBAR(half);

    int buf = 0;
    for (int k0 = 16; k0 <= 256; k0 += 16) {
        const bool more = (k0 < 256);
        if (more) {
            ra = *reinterpret_cast<const float4*>(aptr + k0);
            rb = *reinterpret_cast<const float4*>(bptr + k0);
        }
#pragma unroll
        for (int kk = 0; kk < 16; kk++) {
            ull a[2];
            ulonglong2 t0 = *reinterpret_cast<const ulonglong2*>(&STA(buf, kk, ty * 4));
            a[0] = t0.x; a[1] = t0.y;
            float4 b4 = *reinterpret_cast<const float4*>(&STB(buf, kk, tx * 4));
            ull bd[4];
            bd[0] = dup2(b4.x); bd[1] = dup2(b4.y); bd[2] = dup2(b4.z); bd[3] = dup2(b4.w);
#pragma unroll
            for (int i = 0; i < 2; i++)
#pragma unroll
                for (int j = 0; j < 4; j++)
                    ffma2(acc[i][j], a[i], bd[j]);
        }
        if (more) {
            STA(buf ^ 1, kq + 0, lrow) = ra.x; STA(buf ^ 1, kq + 1, lrow) = ra.y;
            STA(buf ^ 1, kq + 2, lrow) = ra.z; STA(buf ^ 1, kq + 3, lrow) = ra.w;
            STB(buf ^ 1, kq + 0, lrow) = rb.x; STB(buf ^ 1, kq + 1, lrow) = rb.y;
            STB(buf ^ 1, kq + 2, lrow) = rb.z; STB(buf ^ 1, kq + 3, lrow) = rb.w;
        }
        HBAR(half);
        buf ^= 1;
    }

    const int nb = n0 + tx * 4;
#pragma unroll
    for (int p = 0; p < 2; p++) {
        float2 c0 = unpk(acc[p][0]), c1 = unpk(acc[p][1]);
        float2 c2 = unpk(acc[p][2]), c3 = unpk(acc[p][3]);
        float4 row0 = make_float4(c0.x, c1.x, c2.x, c3.x);
        float4 row1 = make_float4(c0.y, c1.y, c2.y, c3.y);
#pragma unroll
        for (int h2 = 0; h2 < 2; h2++) {
            int m = m0 + ty * 4 + 2 * p + h2;
            if (m < nact) {
                int b = g_active[m];
                float4 v = h2 ? row1 : row0;
                if (ks == 0) {
                    size_t base = (size_t)(b * NS + 32 + step) * G5;
                    float* dst = (nb < G5) ? (g_vl + base + nb) : (g_vr + base + (nb - G5));
                    *reinterpret_cast<float4*>(dst) = v;
                } else {
                    *reinterpret_cast<float4*>(g_pv + b * 5120 + nb) = v;
                }
            }
        }
    }
    HBAR(half);
}

// ---------------- pair gates + partial logit (t in 0..127) ----------------
__device__ __forceinline__ float pair_body(int b, int key, int Ls, int Rs, int t,
    const float* __restrict__ b_comp, const float* __restrict__ cq)
{
    const float4* vl  = reinterpret_cast<const float4*>(g_vl + (size_t)(b * NS + Ls) * G5);
    const float4* vr  = reinterpret_cast<const float4*>(g_vr + (size_t)(b * NS + Rs) * G5);
    const float4* bc  = reinterpret_cast<const float4*>(b_comp);
    const float4* cl4 = reinterpret_cast<const float4*>(g_c + (size_t)(b * NS + Ls) * HH);
    const float4* cr4 = reinterpret_cast<const float4*>(g_c + (size_t)(b * NS + Rs) * HH);
    const float4* q4  = reinterpret_cast<const float4*>(cq);

    float vi[4], vfl[4], vfr[4], vu[4], vo[4];
    {
        float* dsts[5] = {vi, vfl, vfr, vu, vo};
#pragma unroll
        for (int g = 0; g < 5; g++) {
            float4 a = vl[g * 128 + t], bb = vr[g * 128 + t], c = bc[g * 128 + t];
            dsts[g][0] = a.x + bb.x + c.x; dsts[g][1] = a.y + bb.y + c.y;
            dsts[g][2] = a.z + bb.z + c.z; dsts[g][3] = a.w + bb.w + c.w;
        }
    }
    float4 cl = cl4[t], cr = cr4[t], qv = q4[t];
    float clv[4] = {cl.x, cl.y, cl.z, cl.w};
    float crv[4] = {cr.x, cr.y, cr.z, cr.w};
    float qa[4]  = {qv.x, qv.y, qv.z, qv.w};
    float hh[4], cc[4], part = 0.f;
#pragma unroll
    for (int e = 0; e < 4; e++) {
        float c = clv[e] * sigf(vfl[e] + 1.f) + crv[e] * sigf(vfr[e] + 1.f)
                + tanhf(vu[e]) * sigf(vi[e]);
        float h = sigf(vo[e]) * tanhf(c);
        cc[e] = c; hh[e] = h;
        part = fmaf(qa[e], h, part);
    }
    reinterpret_cast<float4*>(g_ch + (size_t)(b * NS + key) * HH)[t] = make_float4(hh[0], hh[1], hh[2], hh[3]);
    reinterpret_cast<float4*>(g_cc + (size_t)(b * NS + key) * HH)[t] = make_float4(cc[0], cc[1], cc[2], cc[3]);
    return part;
}

// ---------------- plan for batch b at step i (one warp) ----------------
__device__ __forceinline__ void plan_do(int b, int i, int lane, const int* __restrict__ length)
{
    int ell = length[b];
    if (i + 1 < ell) {
        int npairs = 31 - i;
        int seqv = g_seq[b * 32 + lane];
        bool valid = (lane < ell - i - 1);
        float lg = valid ? g_clog[b * NS + seqv] : -1e9f;
        float mx = lg;
#pragma unroll
        for (int o = 16; o; o >>= 1) mx = fmaxf(mx, __shfl_xor_sync(0xffffffffu, mx, o));
        unsigned bal = __ballot_sync(0xffffffffu, lg == mx);
        int k = __ffs(bal) - 1;   // first-max = jnp.argmax

        int s    = 32 + i;
        int sk   = __shfl_sync(0xffffffffu, seqv, k);
        int skm1 = __shfl_sync(0xffffffffu, seqv, (k > 0) ? (k - 1) : 0);
        int skp2 = __shfl_sync(0xffffffffu, seqv, (k + 2 < 32) ? (k + 2) : 31);

        const float4* sh = reinterpret_cast<const float4*>(g_ch + (size_t)(b * NS + sk) * HH);
        const float4* sc = reinterpret_cast<const float4*>(g_cc + (size_t)(b * NS + sk) * HH);
        float4* dh = reinterpret_cast<float4*>(g_h + (size_t)(b * NS + s) * HH);
        float4* dc = reinterpret_cast<float4*>(g_c + (size_t)(b * NS + s) * HH);
#pragma unroll
        for (int r = 0; r < 4; r++) {
            dh[lane + 32 * r] = sh[lane + 32 * r];
            dc[lane + 32 * r] = sc[lane + 32 * r];
        }
        if (lane == 0) {
            int idx = atomicAdd(&g_nact[i], 1);
            g_active[idx] = b;
            g_jobs[b * 2]     = make_int4(skm1, skm1, s, (k >= 1) ? 1 : 0);
            g_jobs[b * 2 + 1] = make_int4(s, s, skp2, (k <= npairs - 2) ? 1 : 0);
        }
        int nxt = __shfl_down_sync(0xffffffffu, seqv, 1);
        g_seq[b * 32 + lane] = (lane < k) ? seqv : ((lane == k) ? s : nxt);
    } else if (lane == 0) {
        g_jobs[b * 2]     = make_int4(0, 0, 0, 0);
        g_jobs[b * 2 + 1] = make_int4(0, 0, 0, 0);
    }
}

// ---------------- the persistent kernel ----------------
__global__ __launch_bounds__(TPB, 1) void persist_k(
    const float* __restrict__ x, const int* __restrict__ length,
    const float* __restrict__ W_word, const float* __restrict__ b_word,
    const float* __restrict__ W_comp, const float* __restrict__ b_comp,
    const float* __restrict__ cq, float* __restrict__ out)
{
    extern __shared__ __align__(16) char dynp[];
    __shared__ int   srow[128];
    __shared__ float sws[16];

    const int tid  = threadIdx.x;
    const int bid  = blockIdx.x;
    const int half = tid >> 8;
    const int t256 = tid & 255;
    const unsigned dynu = smem_u32(dynp);
    int gen = 0;
    if (tid == 0) gen = g_bar_gen;

    // ---- init + pre-split of x / W_word / W_comp ----
    if (bid == 0) {
        int* slen = (int*)dynp;
        if (tid < BB) slen[tid] = length[tid];
        __syncthreads();
        if (tid < BB) {
            int s = 0;
            for (int q = 0; q < tid; q++) s += slen[q];
            int l = slen[tid];
            for (int k = 0; k < l; k++) g_rowmap[s + k] = tid * 32 + k;
            if (tid == BB - 1) g_nrow = s + l;
        }
    }
    if (bid == 1) {
        for (int idx = tid; idx < BB * 32; idx += TPB) g_seq[idx] = idx & 31;
        if (tid < 32) g_nact[tid] = 0;
    }
    if (bid >= 4) {
        const int NX4 = 8192 * 128, NW4 = 1024 * 128, NC4 = 5120 * 128;
        const int TOT = NX4 + NW4 + NC4;
        for (int i = (bid - 4) * TPB + tid; i < TOT; i += 144 * TPB) {
            float4 f; ull o0, o1, o2;
            if (i < NX4) {
                f = reinterpret_cast<const float4*>(x)[i];
                split4(f, o0, o1, o2);
                size_t e = (size_t)i * 4;
                *reinterpret_cast<ull*>(g_xs + e)          = o0;
                *reinterpret_cast<ull*>(g_xs + XS + e)     = o1;
                *reinterpret_cast<ull*>(g_xs + 2 * XS + e) = o2;
            } else if (i < NX4 + NW4) {
                int j = i - NX4;
                f = reinterpret_cast<const float4*>(W_word)[j];
                split4(f, o0, o1, o2);
                size_t e = (size_t)j * 4;
                *reinterpret_cast<ull*>(g_wws + e)          = o0;
                *reinterpret_cast<ull*>(g_wws + WW + e)     = o1;
                *reinterpret_cast<ull*>(g_wws + 2 * WW + e) = o2;
            } else {
                int j = i - NX4 - NW4;
                int row = j >> 7, kq4 = (j & 127) * 4;
                size_t src = (row < G5) ? ((size_t)row * 1024 + kq4)
                                        : ((size_t)(row - G5) * 1024 + 512 + kq4);
                f = *reinterpret_cast<const float4*>(W_comp + src);
                split4(f, o0, o1, o2);
                size_t e = (size_t)j * 4;
                *reinterpret_cast<ull*>(g_wcs + e)          = o0;
                *reinterpret_cast<ull*>(g_wcs + WC + e)     = o1;
                *reinterpret_cast<ull*>(g_wcs + 2 * WC + e) = o2;
            }
        }
    }
    gbar(tid, &gen);

    const int NROW = g_nrow;
    const int MG   = (NROW + 127) >> 7;

    // ---- phase A: word projection (mma) ----
    for (int tt = bid; tt < MG * 8; tt += GRID)
        gemm_big_mma(0, (tt >> 3) * 128, (tt & 7) * 128, NROW, tid, dynp, dynu, srow, b_word);
    gbar(tid, &gen);

    // ---- phase A': split g_h leaf rows -> g_hs ----
    {
        for (int i = bid * TPB + tid; i < 8192 * 128; i += GRID * TPB) {
            int row = i >> 7, kq4 = (i & 127) * 4;
            int slot = ((row >> 5) << 6) + (row & 31);
            float4 f = *reinterpret_cast<const float4*>(g_h + (size_t)slot * 512 + kq4);
            ull o0, o1, o2;
            split4(f, o0, o1, o2);
            size_t e = (size_t)i * 4;
            *reinterpret_cast<ull*>(g_hs + e)          = o0;
            *reinterpret_cast<ull*>(g_hs + HS + e)     = o1;
            *reinterpret_cast<ull*>(g_hs + 2 * HS + e) = o2;
        }
    }
    gbar(tid, &gen);

    // ---- phase B: leaf transforms (mma) ----
    for (int tt = bid; tt < MG * 40; tt += GRID)
        gemm_big_mma(1, (tt / 40) * 128, (tt % 40) * 128, NROW, tid, dynp, dynu, srow, b_word);
    gbar(tid, &gen);

    // ---- phase C: initial candidates ----
    {
        const int grp = tid >> 7, t2 = tid & 127, w4 = (tid >> 5) & 3;
        for (int p = bid; p < 1984; p += GRID) {
            int j  = p * 4 + grp;
            int b  = j / 31;
            int jj = j - b * 31;
            bool valid = (jj + 1 < length[b]);
            float part = valid ? pair_body(b, jj, jj, jj + 1, t2, b_comp, cq) : 0.f;
#pragma unroll
            for (int o = 16; o; o >>= 1) part += __shfl_xor_sync(0xffffffffu, part, o);
            if ((t2 & 31) == 0) sws[grp * 4 + w4] = part;
            __syncthreads();
            if (t2 == 0 && valid)
                g_clog[b * NS + jj] = (sws[grp*4] + sws[grp*4+1] + sws[grp*4+2] + sws[grp*4+3])
                                      * 0.044194173824159216f;
            __syncthreads();
        }
    }
    gbar(tid, &gen);

    // ---- plan(0) ----
    {
        int b = bid * 2 + half;
        if (b < BB && t256 < 32) plan_do(b, 0, tid & 31, length);
    }
    gbar(tid, &gen);

    // ---- main loop ----
    for (int i = 0; i < 30; i++) {
        {
            int nact   = g_nact[i];
            int ntile2 = (((nact + 63) >> 6) * 80) * 2;
            char* hs = dynp + half * HALF_OFF;
            for (int w = half * GRID + bid; w < ntile2; w += 2 * GRID) {
                int tile = w >> 1, ks = w & 1;
                gemm_step(i, nact, (tile / 80) * 64, (tile % 80) * 64, ks, t256, half, hs, W_comp);
            }
        }
        gbar(tid, &gen);

        {
            int b = bid * 2 + half;
            bool bact = (b < BB);
            bool bmerged = bact && (i + 1 < length[b]);

            if (bmerged) {
                int s = 32 + i;
                const float4* pv = reinterpret_cast<const float4*>(g_pv + b * 5120);
                float4* vl = reinterpret_cast<float4*>(g_vl + (size_t)(b * NS + s) * G5);
                float4* vr = reinterpret_cast<float4*>(g_vr + (size_t)(b * NS + s) * G5);
#pragma unroll
                for (int q = 0; q < 5; q++) {
                    int idx = q * 256 + t256;
                    float4 p = pv[idx];
                    float4* dst = (idx < 640) ? (vl + idx) : (vr + idx - 640);
                    float4 v = *dst;
                    v.x += p.x; v.y += p.y; v.z += p.z; v.w += p.w;
                    *dst = v;
                }
            }
            __syncthreads();

            const int grp = tid >> 7, t2 = tid & 127, w4 = (tid >> 5) & 3;
            int4 job = make_int4(0, 0, 0, 0);
            if (bact) job = g_jobs[b * 2 + (t256 >> 7)];
            bool jact = bact && job.w;
            float part = jact ? pair_body(b, job.x, job.y, job.z, t2, b_comp, cq) : 0.f;
#pragma unroll
            for (int o = 16; o; o >>= 1) part += __shfl_xor_sync(0xffffffffu, part, o);
            if ((t2 & 31) == 0) sws[grp * 4 + w4] = part;
            __syncthreads();
            if (t2 == 0 && jact)
                g_clog[b * NS + job.x] = (sws[grp*4] + sws[grp*4+1] + sws[grp*4+2] + sws[grp*4+3])
                                         * 0.044194173824159216f;
            __syncthreads();
            if (bact && t256 < 32) plan_do(b, i + 1, tid & 31, length);
        }
        gbar(tid, &gen);
    }

    // ---- output ----
    {
        int b = bid * 2 + half;
        if (b < BB && t256 < 128) {
            int s = g_seq[b * 32];
            const float4* src = reinterpret_cast<const float4*>(g_h + (size_t)(b * NS + s) * HH);
            reinterpret_cast<float4*>(out)[b * 128 + t256] = src[t256];
        }
    }
}

// ---------------- launch ----------------
extern "C" void kernel_launch(void* const* d_in, const int* in_sizes, int n_in,
                              void* d_out, int out_size)
{
    const float* x      = (const float*)d_in[0];
    const int*   length = (const int*)  d_in[1];
    const float* W_word = (const float*)d_in[2];
    const float* b_word = (const float*)d_in[3];
    const float* W_comp = (const float*)d_in[4];
    const float* b_comp = (const float*)d_in[5];
    const float* cq     = (const float*)d_in[6];
    float* out = (float*)d_out;

    cudaFuncSetAttribute(persist_k, cudaFuncAttributeMaxDynamicSharedMemorySize, DYN_BYTES);
    persist_k<<<GRID, TPB, DYN_BYTES>>>(x, length, W_word, b_word, W_comp, b_comp, cq, out);
}

// round 15
// speedup vs baseline: 1.0266x; 1.0041x over previous
#include <cuda_runtime.h>
#include <cuda_bf16.h>
#include <math.h>

#define BB   256
#define HH   512
#define DD   512
#define NS   64
#define G5   2560
#define GRID 148
#define TPB  512

#define DYN_BYTES 73728
#define MMA_B_OFF 36864
#define MMA_BUFS  18432
#define MMA_SPL   6144
#define STB_OFF   8704
#define HALF_OFF  17408

#define XS (8192 * 512)
#define WW (1024 * 512)
#define WC (5120 * 512)
#define HS (8192 * 512)

typedef unsigned long long ull;

// ---------------- helpers ----------------
__device__ __forceinline__ ull dup2(float a) {
    ull d; asm("mov.b64 %0, {%1, %1};" : "=l"(d) : "f"(a)); return d;
}
__device__ __forceinline__ void ffma2(ull& acc, ull a, ull b) {
    asm("fma.rn.f32x2 %0, %1, %2, %0;" : "+l"(acc) : "l"(a), "l"(b));
}
__device__ __forceinline__ float2 unpk(ull v) {
    float2 r; asm("mov.b64 {%0, %1}, %2;" : "=f"(r.x), "=f"(r.y) : "l"(v)); return r;
}
__device__ __forceinline__ unsigned smem_u32(const void* p) {
    unsigned a;
    asm("{ .reg .u64 t; cvta.to.shared.u64 t, %1; cvt.u32.u64 %0, t; }" : "=r"(a) : "l"(p));
    return a;
}
#define HBAR(h) asm volatile("bar.sync %0, 256;" :: "r"((h) + 1) : "memory")

#define LDSM4(r, addr) asm volatile( \
    "ldmatrix.sync.aligned.m8n8.x4.shared.b16 {%0,%1,%2,%3}, [%4];" \
    : "=r"((r)[0]), "=r"((r)[1]), "=r"((r)[2]), "=r"((r)[3]) : "r"(addr))

#define MMA16816(d, a, b0, b1) asm volatile( \
    "mma.sync.aligned.m16n8k16.row.col.f32.bf16.bf16.f32 " \
    "{%0,%1,%2,%3}, {%4,%5,%6,%7}, {%8,%9}, {%0,%1,%2,%3};" \
    : "+f"((d)[0]), "+f"((d)[1]), "+f"((d)[2]), "+f"((d)[3]) \
    : "r"((a)[0]), "r"((a)[1]), "r"((a)[2]), "r"((a)[3]), "r"(b0), "r"(b1))

__device__ __forceinline__ ull pk2(__nv_bfloat162 a, __nv_bfloat162 b) {
    unsigned x = *reinterpret_cast<unsigned*>(&a);
    unsigned y = *reinterpret_cast<unsigned*>(&b);
    return (ull)x | ((ull)y << 32);
}
__device__ __forceinline__ void split4(float4 f, ull& o0, ull& o1, ull& o2)
{
    __nv_bfloat162 p0 = __floats2bfloat162_rn(f.x, f.y);
    __nv_bfloat162 q0 = __floats2bfloat162_rn(f.z, f.w);
    float ax = f.x - __bfloat162float(p0.x), ay = f.y - __bfloat162float(p0.y);
    float az = f.z - __bfloat162float(q0.x), aw = f.w - __bfloat162float(q0.y);
    __nv_bfloat162 p1 = __floats2bfloat162_rn(ax, ay);
    __nv_bfloat162 q1 = __floats2bfloat162_rn(az, aw);
    float bx = ax - __bfloat162float(p1.x), by = ay - __bfloat162float(p1.y);
    float bz = az - __bfloat162float(q1.x), bw2 = aw - __bfloat162float(q1.y);
    __nv_bfloat162 p2 = __floats2bfloat162_rn(bx, by);
    __nv_bfloat162 q2 = __floats2bfloat162_rn(bz, bw2);
    o0 = pk2(p0, q0); o1 = pk2(p1, q1); o2 = pk2(p2, q2);
}
// fp32 pair -> 3-term bf16x2 split (for fused epilogue)
__device__ __forceinline__ void split2(float v0, float v1,
    __nv_bfloat162& s0, __nv_bfloat162& s1, __nv_bfloat162& s2)
{
    s0 = __floats2bfloat162_rn(v0, v1);
    float a0 = v0 - __bfloat162float(s0.x), a1 = v1 - __bfloat162float(s0.y);
    s1 = __floats2bfloat162_rn(a0, a1);
    float b0 = a0 - __bfloat162float(s1.x), b1 = a1 - __bfloat162float(s1.y);
    s2 = __floats2bfloat162_rn(b0, b1);
}

// ---------------- static device scratch ----------------
__device__ float g_h [BB * NS * HH];
__device__ float g_c [BB * NS * HH];
__device__ float g_ch[BB * NS * HH];
__device__ float g_cc[BB * NS * HH];
__device__ float g_vl[(size_t)BB * NS * G5];
__device__ float g_vr[(size_t)BB * NS * G5];
__device__ float g_pv[BB * 5120];
__device__ float g_clog[BB * NS];
__device__ int   g_seq [BB * 32];
__device__ int4  g_jobs[BB * 2];
__device__ int   g_active[BB];
__device__ int   g_nact[32];
__device__ int   g_rowmap[BB * 32];
__device__ int   g_nrow;
__device__ int   g_bar_cnt = 0;
__device__ volatile int g_bar_gen = 0;
__device__ __nv_bfloat16 g_xs [3 * XS];
__device__ __nv_bfloat16 g_wws[3 * WW];
__device__ __nv_bfloat16 g_wcs[3 * WC];
__device__ __nv_bfloat16 g_hs [3 * HS];

__device__ __forceinline__ float sigf(float x) { return 1.f / (1.f + expf(-x)); }

// ---------------- software grid barrier ----------------
__device__ __forceinline__ void gbar(int tid, int* gen)
{
    __syncthreads();
    if (tid == 0) {
        int target = *gen + 1;
        __threadfence();
        if (atomicAdd(&g_bar_cnt, 1) == GRID - 1) {
            g_bar_cnt = 0;
            __threadfence();
            g_bar_gen = target;
        } else {
            while (g_bar_gen - target < 0) __nanosleep(32);
            __threadfence();
        }
        *gen = target;
    }
    __syncthreads();
}

// ---------------- big GEMM tile via mma.sync: 128x128xK512, bf16 x3 split ----
// mode 0: A = g_xs[rowmap], B = g_wws, +bias -> g_h/g_c (+ fused g_hs split)
// mode 1: A = g_hs[rowmap], B = g_wcs           -> g_vl/g_vr
__device__ void gemm_big_mma(int mode, int m0, int n0, int NROW, int tid,
    char* dynp, unsigned dynu, int* __restrict__ srow, const float* __restrict__ bw)
{
    __syncthreads();
    if (tid < 128) {
        int r = m0 + tid;
        srow[tid] = (r < NROW) ? g_rowmap[r] : g_rowmap[0];
    }
    __syncthreads();

    const int arow = tid >> 2;
    const int kq   = (tid & 3) * 4;
    const __nv_bfloat16 *aS0, *bS0;
    {
        size_t aoff = (size_t)srow[arow] * 512 + kq;
        size_t boff = (size_t)(n0 + arow) * 512 + kq;
        aS0 = (mode == 0 ? g_xs : g_hs) + aoff;
        bS0 = (mode == 0 ? g_wws : g_wcs) + boff;
    }
    const size_t aStr = (mode == 0) ? XS : HS;
    const size_t bStr = (mode == 0) ? WW : WC;
    char* stsA = dynp + arow * 48 + kq * 2;
    char* stsB = dynp + MMA_B_OFF + arow * 48 + kq * 2;

    const int lane = tid & 31, wid = tid >> 5;
    const int wm = wid >> 2, wn = wid & 3;
    const unsigned ldA = dynu + (unsigned)((wm * 32 + (lane & 15)) * 48 + (lane >> 4) * 16);
    const int lrB = (lane & 7) + ((lane >> 4) << 3);
    const unsigned ldB = dynu + MMA_B_OFF + (unsigned)((wn * 32 + lrB) * 48 + ((lane >> 3) & 1) * 16);

    float acc[2][4][4];
#pragma unroll
    for (int i = 0; i < 2; i++)
#pragma unroll
        for (int j = 0; j < 4; j++)
#pragma unroll
            for (int q = 0; q < 4; q++) acc[i][j][q] = 0.f;

#pragma unroll
    for (int s = 0; s < 3; s++) {
        *reinterpret_cast<ull*>(stsA + s * MMA_SPL) = *reinterpret_cast<const ull*>(aS0 + s * aStr);
        *reinterpret_cast<ull*>(stsB + s * MMA_SPL) = *reinterpret_cast<const ull*>(bS0 + s * bStr);
    }
    __syncthreads();

    for (int kc = 0; kc < 32; kc++) {
        const int bo = (kc & 1) * MMA_BUFS;
        const bool more = (kc < 31);
        ull pa[3], pb[3];
        if (more) {
            int ko = (kc + 1) * 16;
#pragma unroll
            for (int s = 0; s < 3; s++) {
                pa[s] = *reinterpret_cast<const ull*>(aS0 + s * aStr + ko);
                pb[s] = *reinterpret_cast<const ull*>(bS0 + s * bStr + ko);
            }
        }
        unsigned a[3][2][4];
#pragma unroll
        for (int s = 0; s < 3; s++)
#pragma unroll
            for (int mt = 0; mt < 2; mt++)
                LDSM4(a[s][mt], ldA + bo + s * MMA_SPL + mt * 768);
#pragma unroll
        for (int sb = 0; sb < 3; sb++) {
            unsigned b[2][4];
#pragma unroll
            for (int np = 0; np < 2; np++)
                LDSM4(b[np], ldB + bo + sb * MMA_SPL + np * 768);
#pragma unroll
            for (int sa = 0; sa < 3; sa++) {
                if (sa + sb < 3) {
#pragma unroll
                    for (int mt = 0; mt < 2; mt++)
#pragma unroll
                        for (int np = 0; np < 2; np++) {
                            MMA16816(acc[mt][np * 2],     a[sa][mt], b[np][0], b[np][1]);
                            MMA16816(acc[mt][np * 2 + 1], a[sa][mt], b[np][2], b[np][3]);
                        }
                }
            }
        }
        if (more) {
            int bo2 = ((kc + 1) & 1) * MMA_BUFS;
#pragma unroll
            for (int s = 0; s < 3; s++) {
                *reinterpret_cast<ull*>(stsA + bo2 + s * MMA_SPL) = pa[s];
                *reinterpret_cast<ull*>(stsB + bo2 + s * MMA_SPL) = pb[s];
            }
        }
        __syncthreads();
    }

    // epilogue
#pragma unroll
    for (int mt = 0; mt < 2; mt++)
#pragma unroll
        for (int nt8 = 0; nt8 < 4; nt8++) {
            int col = wn * 32 + nt8 * 8 + (lane & 3) * 2;
            int nc  = n0 + col;
#pragma unroll
            for (int hfl = 0; hfl < 2; hfl++) {
                int r = wm * 32 + mt * 16 + (lane >> 2) + hfl * 8;
                if (m0 + r < NROW) {
                    int m = srow[r];
                    int slot = ((m >> 5) << 6) + (m & 31);
                    float v0 = acc[mt][nt8][hfl * 2], v1 = acc[mt][nt8][hfl * 2 + 1];
                    if (mode == 0) {
                        v0 += bw[nc]; v1 += bw[nc + 1];
                        if (nc < HH) {
                            *reinterpret_cast<float2*>(g_h + (size_t)slot * HH + nc)
                                = make_float2(v0, v1);
                            // fused split of h into g_hs (3 terms)
                            __nv_bfloat162 s0, s1, s2;
                            split2(v0, v1, s0, s1, s2);
                            size_t e = (size_t)m * 512 + nc;
                            *reinterpret_cast<__nv_bfloat162*>(g_hs + e)          = s0;
                            *reinterpret_cast<__nv_bfloat162*>(g_hs + HS + e)     = s1;
                            *reinterpret_cast<__nv_bfloat162*>(g_hs + 2 * HS + e) = s2;
                        } else {
                            *reinterpret_cast<float2*>(g_c + (size_t)slot * HH + (nc - HH))
                                = make_float2(v0, v1);
                        }
                    } else {
                        size_t base = (size_t)slot * G5;
                        float* dst = (nc < G5) ? (g_vl + base + nc) : (g_vr + base + (nc - G5));
                        *reinterpret_cast<float2*>(dst) = make_float2(v0, v1);
                    }
                }
            }
        }
    __syncthreads();
}

// ---------------- step GEMM half-tile: 64x64xK256 (split-K), FFMA2 ----------------
#define STA(buf,k,r) Af[((buf)*16 + (k))*68 + (r)]
#define STB(buf,k,r) Bf[((buf)*16 + (k))*68 + (r)]
__device__ void gemm_step(int step, int nact, int m0, int n0, int ks, int t, int half,
    char* hs, const float* __restrict__ Wc)
{
    float* Af = (float*)hs;
    float* Bf = (float*)(hs + STB_OFF);

    const int lrow = t >> 2;
    const int kq   = (t & 3) * 4;
    const int kofs = ks * 256;

    const float* aptr;
    {
        int m = m0 + lrow;
        int b = (m < nact) ? g_active[m] : g_active[0];
        aptr = g_h + (size_t)(b * NS + 32 + step) * HH + kofs + kq;
    }
    const float* bptr;
    {
        int n = n0 + lrow;
        bptr = (n < G5) ? Wc + (size_t)n * 1024 + kofs + kq
                        : Wc + (size_t)(n - G5) * 1024 + 512 + kofs + kq;
    }

    const int ty = t >> 4;
    const int tx = t & 15;

    ull acc[2][4];
#pragma unroll
    for (int i = 0; i < 2; i++)
#pragma unroll
        for (int j = 0; j < 4; j++) acc[i][j] = 0ull;

    float4 ra = *reinterpret_cast<const float4*>(aptr);
    float4 rb = *reinterpret_cast<const float4*>(bptr);
    STA(0, kq + 0, lrow) = ra.x; STA(0, kq + 1, lrow) = ra.y;
    STA(0, kq + 2, lrow) = ra.z; STA(0, kq + 3, lrow) = ra.w;
    STB(0, kq + 0, lrow) = rb.x; STB(0, kq + 1, lrow) = rb.y;
    STB(0, kq + 2, lrow) = rb.z; STB(0, kq + 3, lrow) = rb.w;
    HBAR(half);

    int buf = 0;
    for (int k0 = 16; k0 <= 256; k0 += 16) {
        const bool more = (k0 < 256);
        if (more) {
            ra = *reinterpret_cast<const float4*>(aptr + k0);
            rb = *reinterpret_cast<const float4*>(bptr + k0);
        }
#pragma unroll
        for (int kk = 0; kk < 16; kk++) {
            ull a[2];
            ulonglong2 t0 = *reinterpret_cast<const ulonglong2*>(&STA(buf, kk, ty * 4));
            a[0] = t0.x; a[1] = t0.y;
            float4 b4 = *reinterpret_cast<const float4*>(&STB(buf, kk, tx * 4));
            ull bd[4];
            bd[0] = dup2(b4.x); bd[1] = dup2(b4.y); bd[2] = dup2(b4.z); bd[3] = dup2(b4.w);
#pragma unroll
            for (int i = 0; i < 2; i++)
#pragma unroll
                for (int j = 0; j < 4; j++)
                    ffma2(acc[i][j], a[i], bd[j]);
        }
        if (more) {
            STA(buf ^ 1, kq + 0, lrow) = ra.x; STA(buf ^ 1, kq + 1, lrow) = ra.y;
            STA(buf ^ 1, kq + 2, lrow) = ra.z; STA(buf ^ 1, kq + 3, lrow) = ra.w;
            STB(buf ^ 1, kq + 0, lrow) = rb.x; STB(buf ^ 1, kq + 1, lrow) = rb.y;
            STB(buf ^ 1, kq + 2, lrow) = rb.z; STB(buf ^ 1, kq + 3, lrow) = rb.w;
        }
        HBAR(half);
        buf ^= 1;
    }

    const int nb = n0 + tx * 4;
#pragma unroll
    for (int p = 0; p < 2; p++) {
        float2 c0 = unpk(acc[p][0]), c1 = unpk(acc[p][1]);
        float2 c2 = unpk(acc[p][2]), c3 = unpk(acc[p][3]);
        float4 row0 = make_float4(c0.x, c1.x, c2.x, c3.x);
        float4 row1 = make_float4(c0.y, c1.y, c2.y, c3.y);
#pragma unroll
        for (int h2 = 0; h2 < 2; h2++) {
            int m = m0 + ty * 4 + 2 * p + h2;
            if (m < nact) {
                int b = g_active[m];
                float4 v = h2 ? row1 : row0;
                if (ks == 0) {
                    size_t base = (size_t)(b * NS + 32 + step) * G5;
                    float* dst = (nb < G5) ? (g_vl + base + nb) : (g_vr + base + (nb - G5));
                    *reinterpret_cast<float4*>(dst) = v;
                } else {
                    *reinterpret_cast<float4*>(g_pv + b * 5120 + nb) = v;
                }
            }
        }
    }
    HBAR(half);
}

// ---------------- pair gates + partial logit ----------------
__device__ __forceinline__ float pair_body(int b, int key, int Ls, int Rs, int t,
    const float* __restrict__ b_comp, const float* __restrict__ cq)
{
    const float4* vl  = reinterpret_cast<const float4*>(g_vl + (size_t)(b * NS + Ls) * G5);
    const float4* vr  = reinterpret_cast<const float4*>(g_vr + (size_t)(b * NS + Rs) * G5);
    const float4* bc  = reinterpret_cast<const float4*>(b_comp);
    const float4* cl4 = reinterpret_cast<const float4*>(g_c + (size_t)(b * NS + Ls) * HH);
    const float4* cr4 = reinterpret_cast<const float4*>(g_c + (size_t)(b * NS + Rs) * HH);
    const float4* q4  = reinterpret_cast<const float4*>(cq);

    float vi[4], vfl[4], vfr[4], vu[4], vo[4];
    {
        float* dsts[5] = {vi, vfl, vfr, vu, vo};
#pragma unroll
        for (int g = 0; g < 5; g++) {
            float4 a = vl[g * 128 + t], bb = vr[g * 128 + t], c = bc[g * 128 + t];
            dsts[g][0] = a.x + bb.x + c.x; dsts[g][1] = a.y + bb.y + c.y;
            dsts[g][2] = a.z + bb.z + c.z; dsts[g][3] = a.w + bb.w + c.w;
        }
    }
    float4 cl = cl4[t], cr = cr4[t], qv = q4[t];
    float clv[4] = {cl.x, cl.y, cl.z, cl.w};
    float crv[4] = {cr.x, cr.y, cr.z, cr.w};
    float qa[4]  = {qv.x, qv.y, qv.z, qv.w};
    float hh[4], cc[4], part = 0.f;
#pragma unroll
    for (int e = 0; e < 4; e++) {
        float c = clv[e] * sigf(vfl[e] + 1.f) + crv[e] * sigf(vfr[e] + 1.f)
                + tanhf(vu[e]) * sigf(vi[e]);
        float h = sigf(vo[e]) * tanhf(c);
        cc[e] = c; hh[e] = h;
        part = fmaf(qa[e], h, part);
    }
    reinterpret_cast<float4*>(g_ch + (size_t)(b * NS + key) * HH)[t] = make_float4(hh[0], hh[1], hh[2], hh[3]);
    reinterpret_cast<float4*>(g_cc + (size_t)(b * NS + key) * HH)[t] = make_float4(cc[0], cc[1], cc[2], cc[3]);
    return part;
}

// ---------------- plan ----------------
__device__ __forceinline__ void plan_do(int b, int i, int lane, const int* __restrict__ length)
{
    int ell = length[b];
    if (i + 1 < ell) {
        int npairs = 31 - i;
        int seqv = g_seq[b * 32 + lane];
        bool valid = (lane < ell - i - 1);
        float lg = valid ? g_clog[b * NS + seqv] : -1e9f;
        float mx = lg;
#pragma unroll
        for (int o = 16; o; o >>= 1) mx = fmaxf(mx, __shfl_xor_sync(0xffffffffu, mx, o));
        unsigned bal = __ballot_sync(0xffffffffu, lg == mx);
        int k = __ffs(bal) - 1;

        int s    = 32 + i;
        int sk   = __shfl_sync(0xffffffffu, seqv, k);
        int skm1 = __shfl_sync(0xffffffffu, seqv, (k > 0) ? (k - 1) : 0);
        int skp2 = __shfl_sync(0xffffffffu, seqv, (k + 2 < 32) ? (k + 2) : 31);

        const float4* sh = reinterpret_cast<const float4*>(g_ch + (size_t)(b * NS + sk) * HH);
        const float4* sc = reinterpret_cast<const float4*>(g_cc + (size_t)(b * NS + sk) * HH);
        float4* dh = reinterpret_cast<float4*>(g_h + (size_t)(b * NS + s) * HH);
        float4* dc = reinterpret_cast<float4*>(g_c + (size_t)(b * NS + s) * HH);
#pragma unroll
        for (int r = 0; r < 4; r++) {
            dh[lane + 32 * r] = sh[lane + 32 * r];
            dc[lane + 32 * r] = sc[lane + 32 * r];
        }
        if (lane == 0) {
            int idx = atomicAdd(&g_nact[i], 1);
            g_active[idx] = b;
            g_jobs[b * 2]     = make_int4(skm1, skm1, s, (k >= 1) ? 1 : 0);
            g_jobs[b * 2 + 1] = make_int4(s, s, skp2, (k <= npairs - 2) ? 1 : 0);
        }
        int nxt = __shfl_down_sync(0xffffffffu, seqv, 1);
        g_seq[b * 32 + lane] = (lane < k) ? seqv : ((lane == k) ? s : nxt);
    } else if (lane == 0) {
        g_jobs[b * 2]     = make_int4(0, 0, 0, 0);
        g_jobs[b * 2 + 1] = make_int4(0, 0, 0, 0);
    }
}

// ---------------- the persistent kernel ----------------
__global__ __launch_bounds__(TPB, 1) void persist_k(
    const float* __restrict__ x, const int* __restrict__ length,
    const float* __restrict__ W_word, const float* __restrict__ b_word,
    const float* __restrict__ W_comp, const float* __restrict__ b_comp,
    const float* __restrict__ cq, float* __restrict__ out)
{
    extern __shared__ __align__(16) char dynp[];
    __shared__ int   srow[128];
    __shared__ float sws[16];

    const int tid  = threadIdx.x;
    const int bid  = blockIdx.x;
    const int half = tid >> 8;
    const int t256 = tid & 255;
    const unsigned dynu = smem_u32(dynp);
    int gen = 0;
    if (tid == 0) gen = g_bar_gen;

    // ---- init + pre-split of x / W_word / W_comp ----
    if (bid == 0) {
        int* slen = (int*)dynp;
        if (tid < BB) slen[tid] = length[tid];
        __syncthreads();
        if (tid < BB) {
            int s = 0;
            for (int q = 0; q < tid; q++) s += slen[q];
            int l = slen[tid];
            for (int k = 0; k < l; k++) g_rowmap[s + k] = tid * 32 + k;
            if (tid == BB - 1) g_nrow = s + l;
        }
    }
    if (bid == 1) {
        for (int idx = tid; idx < BB * 32; idx += TPB) g_seq[idx] = idx & 31;
        if (tid < 32) g_nact[tid] = 0;
    }
    if (bid >= 4) {
        const int NX4 = 8192 * 128, NW4 = 1024 * 128, NC4 = 5120 * 128;
        const int TOT = NX4 + NW4 + NC4;
        for (int i = (bid - 4) * TPB + tid; i < TOT; i += 144 * TPB) {
            float4 f; ull o0, o1, o2;
            if (i < NX4) {
                f = reinterpret_cast<const float4*>(x)[i];
                split4(f, o0, o1, o2);
                size_t e = (size_t)i * 4;
                *reinterpret_cast<ull*>(g_xs + e)          = o0;
                *reinterpret_cast<ull*>(g_xs + XS + e)     = o1;
                *reinterpret_cast<ull*>(g_xs + 2 * XS + e) = o2;
            } else if (i < NX4 + NW4) {
                int j = i - NX4;
                f = reinterpret_cast<const float4*>(W_word)[j];
                split4(f, o0, o1, o2);
                size_t e = (size_t)j * 4;
                *reinterpret_cast<ull*>(g_wws + e)          = o0;
                *reinterpret_cast<ull*>(g_wws + WW + e)     = o1;
                *reinterpret_cast<ull*>(g_wws + 2 * WW + e) = o2;
            } else {
                int j = i - NX4 - NW4;
                int row = j >> 7, kq4 = (j & 127) * 4;
                size_t src = (row < G5) ? ((size_t)row * 1024 + kq4)
                                        : ((size_t)(row - G5) * 1024 + 512 + kq4);
                f = *reinterpret_cast<const float4*>(W_comp + src);
                split4(f, o0, o1, o2);
                size_t e = (size_t)j * 4;
                *reinterpret_cast<ull*>(g_wcs + e)          = o0;
                *reinterpret_cast<ull*>(g_wcs + WC + e)     = o1;
                *reinterpret_cast<ull*>(g_wcs + 2 * WC + e) = o2;
            }
        }
    }
    gbar(tid, &gen);

    const int NROW = g_nrow;
    const int MG   = (NROW + 127) >> 7;

    // ---- phase A: word projection (mma) with fused g_hs split ----
    for (int tt = bid; tt < MG * 8; tt += GRID)
        gemm_big_mma(0, (tt >> 3) * 128, (tt & 7) * 128, NROW, tid, dynp, dynu, srow, b_word);
    gbar(tid, &gen);

    // ---- phase B: leaf transforms (mma) ----
    for (int tt = bid; tt < MG * 40; tt += GRID)
        gemm_big_mma(1, (tt / 40) * 128, (tt % 40) * 128, NROW, tid, dynp, dynu, srow, b_word);
    gbar(tid, &gen);

    // ---- phase C: initial candidates ----
    {
        const int grp = tid >> 7, t2 = tid & 127, w4 = (tid >> 5) & 3;
        for (int p = bid; p < 1984; p += GRID) {
            int j  = p * 4 + grp;
            int b  = j / 31;
            int jj = j - b * 31;
            bool valid = (jj + 1 < length[b]);
            float part = valid ? pair_body(b, jj, jj, jj + 1, t2, b_comp, cq) : 0.f;
#pragma unroll
            for (int o = 16; o; o >>= 1) part += __shfl_xor_sync(0xffffffffu, part, o);
            if ((t2 & 31) == 0) sws[grp * 4 + w4] = part;
            __syncthreads();
            if (t2 == 0 && valid)
                g_clog[b * NS + jj] = (sws[grp*4] + sws[grp*4+1] + sws[grp*4+2] + sws[grp*4+3])
                                      * 0.044194173824159216f;
            __syncthreads();
        }
    }
    gbar(tid, &gen);

    // ---- plan(0) ----
    {
        int b = bid * 2 + half;
        if (b < BB && t256 < 32) plan_do(b, 0, tid & 31, length);
    }
    gbar(tid, &gen);

    // ---- main loop ----
    for (int i = 0; i < 30; i++) {
        {
            int nact   = g_nact[i];
            int ntile2 = (((nact + 63) >> 6) * 80) * 2;
            char* hs = dynp + half * HALF_OFF;
            for (int w = half * GRID + bid; w < ntile2; w += 2 * GRID) {
                int tile = w >> 1, ks = w & 1;
                gemm_step(i, nact, (tile / 80) * 64, (tile % 80) * 64, ks, t256, half, hs, W_comp);
            }
        }
        gbar(tid, &gen);

        {
            int b = bid * 2 + half;
            bool bact = (b < BB);
            bool bmerged = bact && (i + 1 < length[b]);

            if (bmerged) {
                int s = 32 + i;
                const float4* pv = reinterpret_cast<const float4*>(g_pv + b * 5120);
                float4* vl = reinterpret_cast<float4*>(g_vl + (size_t)(b * NS + s) * G5);
                float4* vr = reinterpret_cast<float4*>(g_vr + (size_t)(b * NS + s) * G5);
#pragma unroll
                for (int q = 0; q < 5; q++) {
                    int idx = q * 256 + t256;
                    float4 p = pv[idx];
                    float4* dst = (idx < 640) ? (vl + idx) : (vr + idx - 640);
                    float4 v = *dst;
                    v.x += p.x; v.y += p.y; v.z += p.z; v.w += p.w;
                    *dst = v;
                }
            }
            __syncthreads();

            const int grp = tid >> 7, t2 = tid & 127, w4 = (tid >> 5) & 3;
            int4 job = make_int4(0, 0, 0, 0);
            if (bact) job = g_jobs[b * 2 + (t256 >> 7)];
            bool jact = bact && job.w;
            float part = jact ? pair_body(b, job.x, job.y, job.z, t2, b_comp, cq) : 0.f;
#pragma unroll
            for (int o = 16; o; o >>= 1) part += __shfl_xor_sync(0xffffffffu, part, o);
            if ((t2 & 31) == 0) sws[grp * 4 + w4] = part;
            __syncthreads();
            if (t2 == 0 && jact)
                g_clog[b * NS + job.x] = (sws[grp*4] + sws[grp*4+1] + sws[grp*4+2] + sws[grp*4+3])
                                         * 0.044194173824159216f;
            __syncthreads();
            if (bact && t256 < 32) plan_do(b, i + 1, tid & 31, length);
        }
        gbar(tid, &gen);
    }

    // ---- output ----
    {
        int b = bid * 2 + half;
        if (b < BB && t256 < 128) {
            int s = g_seq[b * 32];
            const float4* src = reinterpret_cast<const float4*>(g_h + (size_t)(b * NS + s) * HH);
            reinterpret_cast<float4*>(out)[b * 128 + t256] = src[t256];
        }
    }
}

// ---------------- launch ----------------
extern "C" void kernel_launch(void* const* d_in, const int* in_sizes, int n_in,
                              void* d_out, int out_size)
{
    const float* x      = (const float*)d_in[0];
    const int*   length = (const int*)  d_in[1];
    const float* W_word = (const float*)d_in[2];
    const float* b_word = (const float*)d_in[3];
    const float* W_comp = (const float*)d_in[4];
    const float* b_comp = (const float*)d_in[5];
    const float* cq     = (const float*)d_in[6];
    float* out = (float*)d_out;

    cudaFuncSetAttribute(persist_k, cudaFuncAttributeMaxDynamicSharedMemorySize, DYN_BYTES);
    persist_k<<<GRID, TPB, DYN_BYTES>>>(x, length, W_word, b_word, W_comp, b_comp, cq, out);
}